// round 1
// baseline (speedup 1.0000x reference)
#include <cuda_runtime.h>
#include <math.h>

#define Bv 2
#define Tv 2048
#define NXv 512
#define HDv 128
#define Lv 64
#define KIv 32   // rns indices per row

// ---------------- scratch (device globals; no allocation allowed) ----------------
__device__ float g_q[Bv*Tv*NXv];
__device__ float g_k[Bv*Tv*NXv];
__device__ float g_v[Bv*Tv*NXv];
__device__ float g_a[Bv*Tv*NXv];
__device__ float g_sq[Bv*4*Lv*HDv];
__device__ float g_sk[Bv*4*Lv*HDv];
__device__ float g_w1 [Bv*4*Tv*Lv];   // [b,h,t,j]
__device__ float g_w2t[Bv*4*Tv*Lv];   // [b,h,t',j]
__device__ int   g_cols[Bv*Tv*KIv];
__device__ int   g_cnt [Bv*Tv];
__device__ float g_vpart[8*Bv*NXv];
__device__ float g_vcolsum[Bv*NXv];
__device__ float g_scal[2];           // [lam, 1-lam_init]

// ---------------- lam scalar ----------------
__global__ void lam_kernel(const float* __restrict__ lq1, const float* __restrict__ lk1,
                           const float* __restrict__ lq2, const float* __restrict__ lk2,
                           const int* __restrict__ lptr)
{
    __shared__ float r1[128], r2[128];
    int t = threadIdx.x;
    r1[t] = lq1[t]*lk1[t];
    r2[t] = lq2[t]*lk2[t];
    __syncthreads();
    for (int o = 64; o; o >>= 1) {
        if (t < o) { r1[t] += r1[t+o]; r2[t] += r2[t+o]; }
        __syncthreads();
    }
    if (t == 0) {
        float lam_init = 0.8f - 0.6f*expf(-0.3f*(float)lptr[0]);
        float lam = expf(r1[0]) - expf(r2[0]) + lam_init;
        g_scal[0] = lam;
        g_scal[1] = 1.0f - lam_init;
    }
}

// ---------------- generic TN GEMM tile body: C[M,N] = A[M,K] * B[N,K]^T ----------
// 64x64 block tile, BK=16, 256 threads, 4x4 microtile. M,N,K multiples of 64/64/16.
__device__ __forceinline__ void gemm_tile_64(
    const float* __restrict__ A, int lda,
    const float* __restrict__ Bm, int ldb,
    float* __restrict__ C, int ldc,
    int Kd, int m0, int n0)
{
    __shared__ __align__(16) float As[16][68];
    __shared__ __align__(16) float Bs[16][68];
    const int tid = threadIdx.x;
    const int tx = tid & 15, ty = tid >> 4;
    const int lr = tid >> 2;          // 0..63
    const int lc = (tid & 3) << 2;    // 0,4,8,12
    float acc[4][4] = {};
    const float* Ap = A + (size_t)(m0 + lr)*lda + lc;
    const float* Bp = Bm + (size_t)(n0 + lr)*ldb + lc;
    for (int k0 = 0; k0 < Kd; k0 += 16) {
        float4 av = *(const float4*)(Ap + k0);
        float4 bv = *(const float4*)(Bp + k0);
        As[lc+0][lr]=av.x; As[lc+1][lr]=av.y; As[lc+2][lr]=av.z; As[lc+3][lr]=av.w;
        Bs[lc+0][lr]=bv.x; Bs[lc+1][lr]=bv.y; Bs[lc+2][lr]=bv.z; Bs[lc+3][lr]=bv.w;
        __syncthreads();
#pragma unroll
        for (int kk = 0; kk < 16; ++kk) {
            float4 a = *(const float4*)&As[kk][ty<<2];
            float4 b = *(const float4*)&Bs[kk][tx<<2];
            acc[0][0] += a.x*b.x; acc[0][1] += a.x*b.y; acc[0][2] += a.x*b.z; acc[0][3] += a.x*b.w;
            acc[1][0] += a.y*b.x; acc[1][1] += a.y*b.y; acc[1][2] += a.y*b.z; acc[1][3] += a.y*b.w;
            acc[2][0] += a.z*b.x; acc[2][1] += a.z*b.y; acc[2][2] += a.z*b.z; acc[2][3] += a.z*b.w;
            acc[3][0] += a.w*b.x; acc[3][1] += a.w*b.y; acc[3][2] += a.w*b.z; acc[3][3] += a.w*b.w;
        }
        __syncthreads();
    }
#pragma unroll
    for (int i = 0; i < 4; i++) {
        float4 o;
        o.x = acc[i][0]; o.y = acc[i][1]; o.z = acc[i][2]; o.w = acc[i][3];
        *(float4*)(C + (size_t)(m0 + (ty<<2) + i)*ldc + n0 + (tx<<2)) = o;
    }
}

__global__ void __launch_bounds__(256) gemm_tn(
    const float* __restrict__ A, int lda,
    const float* __restrict__ Bm, int ldb,
    float* __restrict__ C, int ldc, int Kd)
{
    gemm_tile_64(A, lda, Bm, ldb, C, ldc, Kd, blockIdx.x*64, blockIdx.y*64);
}

// w1[b,h,t,j]  = sum_d q[b,t,h*128+d] * sk[b,h,j,d]     (z = 0..5)
// w2t[b,h,t,j] = sum_d k[b,t,h*128+d] * sq[b,h,j,d]     (z = 6..11)
// heads h = 1..3 only (head 0 cancels out of wmix).
__global__ void __launch_bounds__(256) gemm_w()
{
    int z = blockIdx.z;
    int second = (z >= 6);
    int zz = second ? z - 6 : z;
    int b = zz / 3, h = zz % 3 + 1;
    const float* A  = (second ? g_k : g_q) + (size_t)b*Tv*NXv + h*HDv;
    const float* Bm = (second ? g_sq : g_sk) + (size_t)((b*4+h)*Lv)*HDv;
    float* C = (second ? g_w2t : g_w1) + (size_t)((b*4+h)*Tv)*Lv;
    gemm_tile_64(A, NXv, Bm, HDv, C, Lv, HDv, blockIdx.x*64, 0);
}

// ---------------- sq / sk: gather landmark rows, L2-normalize over d, scale -------
// grid.x = 2*B*3*L, 128 threads = one 128-dim vector.
__global__ void sqsk_kernel(const int* __restrict__ landmark,
                            const float* __restrict__ m1,
                            const float* __restrict__ m2)
{
    int idx = blockIdx.x;
    int which = idx & 1;            // 0: sq (from q, m1)   1: sk (from k, m2)
    int rest = idx >> 1;
    int j  = rest % Lv;
    int hm = (rest / Lv) % 3;
    int b  = rest / (Lv*3);
    int h  = hm + 1;
    int t  = threadIdx.x;           // 0..127
    int tok = landmark[j];
    const float* src = (which ? g_k : g_q) + (size_t)(b*Tv + tok)*NXv + h*HDv;
    float v = src[t];
    __shared__ float red[128];
    red[t] = v*v;
    __syncthreads();
    for (int o = 64; o; o >>= 1) { if (t < o) red[t] += red[t+o]; __syncthreads(); }
    float nrm = sqrtf(red[0]);
    float scale = (which ? m2[h*Lv + j] : m1[h*Lv + j]) / nrm;
    float* dst = (which ? g_sk : g_sq) + (size_t)((b*4+h)*Lv + j)*HDv;
    dst[t] = v * scale;
}

// ---------------- symmetric mask -> per-row CSR (dedup) ----------------
__global__ void mask_kernel(const int* __restrict__ rns)
{
    int warp = (blockIdx.x * blockDim.x + threadIdx.x) >> 5;  // row index b*T+i
    int lane = threadIdx.x & 31;
    int b = warp >> 11, i = warp & (Tv-1);
    const int* row = rns + (size_t)warp * KIv;
    int j = row[lane];
    bool dup = false;
#pragma unroll
    for (int k2 = 0; k2 < 32; ++k2) {
        int jj = __shfl_sync(0xffffffffu, j, k2);
        if (k2 < lane && jj == j) dup = true;
    }
    bool mem = false;
    const int* rj = rns + (size_t)(b*Tv + j)*KIv;
#pragma unroll
    for (int m = 0; m < 32; ++m) if (rj[m] == i) mem = true;
    bool valid = (!dup) && mem;
    unsigned bal = __ballot_sync(0xffffffffu, valid);
    if (valid) {
        int pos = __popc(bal & ((1u << lane) - 1u));
        g_cols[(size_t)warp*KIv + pos] = j;
    }
    if (lane == 0) g_cnt[warp] = __popc(bal);
}

// ---------------- column sum of v (for zero-nnz rows), 2-stage deterministic -----
__global__ void colsumA()
{
    int g = blockIdx.x*256 + threadIdx.x;     // 0..8191
    int chunk = g >> 10;                      // 0..7
    int c = g & 1023;                         // b*512+col
    int b = c >> 9, col = c & 511;
    const float* p = g_v + (size_t)(b*Tv + chunk*256)*NXv + col;
    float s = 0.f;
    for (int t = 0; t < 256; ++t) s += p[(size_t)t*NXv];
    g_vpart[g] = s;
}
__global__ void colsumB()
{
    int c = blockIdx.x*256 + threadIdx.x;     // 0..1023
    float s = 0.f;
#pragma unroll
    for (int ch = 0; ch < 8; ++ch) s += g_vpart[ch*1024 + c];
    g_vcolsum[c] = s;
}

// ---------------- per-row sparse attention + wmix + a-gather + RMSNorm -----------
__global__ void __launch_bounds__(256) attn_rows(const float* __restrict__ rms_g)
{
    const int r = blockIdx.x;                 // b*T+i
    const int b = r >> 11;
    const int i = r & (Tv-1);
    const int tid = threadIdx.x;              // 256
    __shared__ int   scols[KIv];
    __shared__ float sw[3][KIv];
    __shared__ float c0[KIv], c1[KIv];
    __shared__ float red[512];
    const int cnt = g_cnt[r];
    if (tid < KIv && tid < cnt) scols[tid] = g_cols[(size_t)r*KIv + tid];
    __syncthreads();
    const float lam = g_scal[0];
    const int wid = tid >> 5, lane = tid & 31;

    // w[h][j] = dot64(w1[b,h,i,:], w2t[b,h,col_j,:]), one warp per task
    for (int task = wid; task < 3*cnt; task += 8) {
        int hm = task % 3, j = task / 3, h = hm + 1;
        const float* w1p = g_w1  + ((size_t)((b*4+h)*Tv + i)        << 6);
        const float* w2p = g_w2t + ((size_t)((b*4+h)*Tv + scols[j]) << 6);
        float s = w1p[lane]*w2p[lane] + w1p[lane+32]*w2p[lane+32];
#pragma unroll
        for (int o = 16; o; o >>= 1) s += __shfl_xor_sync(0xffffffffu, s, o);
        if (lane == 0) sw[hm][j] = s;
    }
    __syncthreads();

    // softmax over nnz per head (warp 0) + wmix coefficients
    if (wid == 0 && cnt > 0) {
        float p[3];
#pragma unroll
        for (int hm = 0; hm < 3; ++hm) {
            float x = (lane < cnt) ? sw[hm][lane] : -INFINITY;
            float mx = x;
#pragma unroll
            for (int o = 16; o; o >>= 1) mx = fmaxf(mx, __shfl_xor_sync(0xffffffffu, mx, o));
            float e = (lane < cnt) ? expf(x - mx) : 0.f;
            float sm = e;
#pragma unroll
            for (int o = 16; o; o >>= 1) sm += __shfl_xor_sync(0xffffffffu, sm, o);
            p[hm] = e / sm;
        }
        if (lane < cnt) {
            // wmix0 = (1-lam)*p2 - lam*p1 ; wmix1 = p2 - p1 + (1-2lam)*p3
            c0[lane] = (1.f - lam)*p[1] - lam*p[0];
            c1[lane] = p[1] - p[0] + (1.f - 2.f*lam)*p[2];
        }
    }
    __syncthreads();

    // a gather (thread tid -> out dims tid and tid+256)
    float s0 = 0.f, s1 = 0.f;
    if (cnt > 0) {
#pragma unroll 4
        for (int j = 0; j < cnt; ++j) {
            const float* vp = g_v + ((size_t)(b*Tv + scols[j]) << 9);
            s0 += c0[j] * vp[tid];
            s1 += c1[j] * vp[tid + 256];
        }
    } else {
        float u = (1.f - 2.f*lam) * (1.f/(float)Tv);
        s0 = u * g_vcolsum[b*NXv + tid];
        s1 = u * g_vcolsum[b*NXv + tid + 256];
    }

    // RMSNorm over each 256-chunk + (1-lam_init) scale
    red[tid]       = s0*s0;
    red[tid + 256] = s1*s1;
    __syncthreads();
#pragma unroll
    for (int o = 128; o; o >>= 1) {
        if (tid < o) { red[tid] += red[tid+o]; red[256+tid] += red[256+tid+o]; }
        __syncthreads();
    }
    float onem = g_scal[1];
    float g = rms_g[tid];
    float sc0 = rsqrtf(red[0]  *(1.f/256.f) + 1e-5f) * g * onem;
    float sc1 = rsqrtf(red[256]*(1.f/256.f) + 1e-5f) * g * onem;
    g_a[(size_t)r*NXv + tid]       = s0 * sc0;
    g_a[(size_t)r*NXv + 256 + tid] = s1 * sc1;
}

// ---------------- launch ----------------
extern "C" void kernel_launch(void* const* d_in, const int* in_sizes, int n_in,
                              void* d_out, int out_size)
{
    const float* x    = (const float*)d_in[0];
    const float* wq   = (const float*)d_in[1];
    const float* wk   = (const float*)d_in[2];
    const float* wv   = (const float*)d_in[3];
    const float* wo   = (const float*)d_in[4];
    const float* m1   = (const float*)d_in[5];
    const float* m2   = (const float*)d_in[6];
    const float* lq1  = (const float*)d_in[7];
    const float* lk1  = (const float*)d_in[8];
    const float* lq2  = (const float*)d_in[9];
    const float* lk2  = (const float*)d_in[10];
    const float* rmsg = (const float*)d_in[11];
    const int*   lp   = (const int*)d_in[12];
    // d_in[13] = num_landmark (unused, L fixed at 64)
    const int*   rns  = (const int*)d_in[14];
    const int*   lmk  = (const int*)d_in[15];
    float* out = (float*)d_out;

    float *q, *k, *v, *a;
    cudaGetSymbolAddress((void**)&q, g_q);
    cudaGetSymbolAddress((void**)&k, g_k);
    cudaGetSymbolAddress((void**)&v, g_v);
    cudaGetSymbolAddress((void**)&a, g_a);

    lam_kernel<<<1, 128>>>(lq1, lk1, lq2, lk2, lp);

    // q/k/v projections: [4096,512] @ [512,512]^T
    dim3 gqkv(Bv*Tv/64, NXv/64, 1);
    gemm_tn<<<gqkv, 256>>>(x, NXv, wq, NXv, q, NXv, NXv);
    gemm_tn<<<gqkv, 256>>>(x, NXv, wk, NXv, k, NXv, NXv);
    gemm_tn<<<gqkv, 256>>>(x, NXv, wv, NXv, v, NXv, NXv);

    sqsk_kernel<<<2*Bv*3*Lv, 128>>>(lmk, m1, m2);

    gemm_w<<<dim3(Tv/64, 1, 12), 256>>>();

    mask_kernel<<<Bv*Tv*32/256, 256>>>(rns);

    colsumA<<<32, 256>>>();
    colsumB<<<4, 256>>>();

    attn_rows<<<Bv*Tv, 256>>>(rmsg);

    // out = a_flat @ wo^T
    gemm_tn<<<gqkv, 256>>>(a, NXv, wo, NXv, out, NXv, NXv);
}

// round 3
// speedup vs baseline: 2.2567x; 2.2567x over previous
#include <cuda_runtime.h>
#include <cuda_bf16.h>
#include <math.h>
#include <cstdint>

#define Bv 2
#define Tv 2048
#define NXv 512
#define HDv 128
#define Lv 64
#define KIv 32

// ================= scratch (device globals; no allocation allowed) =================
__device__ float g_q[Bv*Tv*NXv];
__device__ float g_k[Bv*Tv*NXv];
__device__ float g_v[Bv*Tv*NXv];
__device__ float g_a[Bv*Tv*NXv];
__device__ float g_sq[Bv*4*Lv*HDv];
__device__ float g_sk[Bv*4*Lv*HDv];
__device__ float g_w1 [Bv*4*Tv*Lv];
__device__ float g_w2t[Bv*4*Tv*Lv];
__device__ int   g_cols[Bv*Tv*KIv];
__device__ int   g_cnt [Bv*Tv];
__device__ float g_vpart[8*Bv*NXv];
__device__ float g_vcolsum[Bv*NXv];
__device__ float g_scal[2];
__device__ __nv_bfloat16 g_xh[Bv*Tv*NXv], g_xl[Bv*Tv*NXv];
__device__ __nv_bfloat16 g_ah[Bv*Tv*NXv], g_al[Bv*Tv*NXv];
__device__ __nv_bfloat16 g_wh[4*NXv*NXv], g_wl[4*NXv*NXv];

// ================= helpers =================
__device__ __forceinline__ uint32_t smem_u32(const void* p) {
    uint32_t a;
    asm("{ .reg .u64 t; cvta.to.shared.u64 t, %1; cvt.u32.u64 %0, t; }" : "=r"(a) : "l"(p));
    return a;
}
__device__ __forceinline__ uint32_t sw128(uint32_t off) { return off ^ ((off >> 3) & 0x70); }

#define CP16(dst, src)  asm volatile("cp.async.cg.shared.global [%0], [%1], 16;" :: "r"(dst), "l"(src) : "memory")
#define CP_COMMIT()     asm volatile("cp.async.commit_group;" ::: "memory")

#define LDSM4(r, a) \
    asm volatile("ldmatrix.sync.aligned.m8n8.x4.shared.b16 {%0,%1,%2,%3}, [%4];" \
        : "=r"((r)[0]), "=r"((r)[1]), "=r"((r)[2]), "=r"((r)[3]) : "r"(a))

#define MMA16816(d, a, b) \
    asm volatile("mma.sync.aligned.m16n8k16.row.col.f32.bf16.bf16.f32 " \
        "{%0,%1,%2,%3},{%4,%5,%6,%7},{%8,%9},{%0,%1,%2,%3};" \
        : "+f"((d)[0]), "+f"((d)[1]), "+f"((d)[2]), "+f"((d)[3]) \
        : "r"((a)[0]), "r"((a)[1]), "r"((a)[2]), "r"((a)[3]), "r"((b)[0]), "r"((b)[1]))

// ================= split-bf16 warp-MMA GEMM: C[M,512] = A[M,512] * B[512,512]^T ====
// grid (M/128, 4), 256 threads. Tiles: 128x64 bf16, SW128 swizzled, double buffered.
// smem: 2 stages x 4 tiles (Ah, Al, Bh, Bl) x 16KB = 128KB.
#define GEMM_SMEM_TOTAL (2*4*16384)

__global__ void __launch_bounds__(256) gemm_mma(
    const __nv_bfloat16* __restrict__ Ah, const __nv_bfloat16* __restrict__ Al,
    const __nv_bfloat16* __restrict__ Bh, const __nv_bfloat16* __restrict__ Bl,
    float* __restrict__ C)
{
    extern __shared__ char smem[];
    const uint32_t sb = smem_u32(smem);
    const int tid = threadIdx.x, wid = tid >> 5, lane = tid & 31;
    const int m0 = blockIdx.x * 128, n0 = blockIdx.y * 128;
    const int wm = wid & 1, wn = wid >> 1;      // warp tile: rows wm*64+64, cols wn*32+32

    float acc[4][4][4] = {};

    const __nv_bfloat16* bases[4] = {Ah, Al, Bh, Bl};

    // ---- stage loader: kc-th 64-wide K slab into buffer at dstbase
    auto load_stage = [&](int kc, uint32_t dstbase) {
#pragma unroll
        for (int t = 0; t < 4; ++t) {
            const int rb = (t < 2) ? m0 : n0;
#pragma unroll
            for (int j = 0; j < 4; ++j) {
                int idx = j * 256 + tid;          // 0..1023
                int row = idx >> 3, c = idx & 7;
                const void* src = bases[t] + (size_t)(rb + row) * 512 + kc * 64 + c * 8;
                uint32_t dst = dstbase + t * 16384 + sw128((uint32_t)(row * 128 + c * 16));
                CP16(dst, src);
            }
        }
    };

    load_stage(0, sb);
    CP_COMMIT();

    for (int kc = 0; kc < 8; ++kc) {
        if (kc < 7) {
            load_stage(kc + 1, sb + ((kc + 1) & 1) * 65536);
            CP_COMMIT();
            asm volatile("cp.async.wait_group 1;" ::: "memory");
        } else {
            asm volatile("cp.async.wait_group 0;" ::: "memory");
        }
        __syncthreads();
        const uint32_t sbuf = sb + (kc & 1) * 65536;

#pragma unroll
        for (int kk = 0; kk < 4; ++kk) {
            const int klo = kk * 2;
            uint32_t ah[4][4], al[4][4], bh[4][2], bl[4][2];
            // A fragments: lanes0-7 m0-7/klo, 8-15 m8-15/klo, 16-23 m0-7/khi, 24-31 m8-15/khi
            const int arow = ((lane >> 3) & 1) * 8 + (lane & 7);
            const int achk = klo + (lane >> 4);
#pragma unroll
            for (int f = 0; f < 4; ++f) {
                uint32_t off = sw128((uint32_t)((wm * 64 + f * 16 + arow) * 128 + achk * 16));
                LDSM4(ah[f], sbuf + off);             // Ah tile at +0
                LDSM4(al[f], sbuf + 16384 + off);     // Al tile
            }
            // B fragments: lanes0-7 n0-7/klo, 8-15 n0-7/khi, 16-23 n8-15/klo, 24-31 n8-15/khi
            const int brow = (lane >> 4) * 8 + (lane & 7);
            const int bchk = klo + ((lane >> 3) & 1);
#pragma unroll
            for (int p = 0; p < 2; ++p) {
                uint32_t off = sw128((uint32_t)((wn * 32 + p * 16 + brow) * 128 + bchk * 16));
                uint32_t r[4];
                LDSM4(r, sbuf + 32768 + off);         // Bh tile
                bh[2*p][0] = r[0]; bh[2*p][1] = r[1];
                bh[2*p+1][0] = r[2]; bh[2*p+1][1] = r[3];
                LDSM4(r, sbuf + 49152 + off);         // Bl tile
                bl[2*p][0] = r[0]; bl[2*p][1] = r[1];
                bl[2*p+1][0] = r[2]; bl[2*p+1][1] = r[3];
            }
            // D += Ah*Bh + Ah*Bl + Al*Bh
#pragma unroll
            for (int f = 0; f < 4; ++f)
#pragma unroll
                for (int n = 0; n < 4; ++n) {
                    MMA16816(acc[f][n], ah[f], bh[n]);
                    MMA16816(acc[f][n], ah[f], bl[n]);
                    MMA16816(acc[f][n], al[f], bh[n]);
                }
        }
        __syncthreads();
    }

    // ---- epilogue: d0,d1 -> (row, col..col+1); d2,d3 -> (row+8, ...)
    const int rbase = m0 + wm * 64 + (lane >> 2);
    const int cbase = n0 + wn * 32 + (lane & 3) * 2;
#pragma unroll
    for (int f = 0; f < 4; ++f)
#pragma unroll
        for (int n = 0; n < 4; ++n) {
            float* p0 = C + (size_t)(rbase + f * 16) * 512 + cbase + n * 8;
            *(float2*)p0 = make_float2(acc[f][n][0], acc[f][n][1]);
            *(float2*)(p0 + 8 * 512) = make_float2(acc[f][n][2], acc[f][n][3]);
        }
}

// ================= fp32 -> (hi,lo) bf16 split =================
__global__ void split_kernel(const float2* __restrict__ src,
                             __nv_bfloat162* __restrict__ hi,
                             __nv_bfloat162* __restrict__ lo)
{
    int i = blockIdx.x * 256 + threadIdx.x;
    float2 v = src[i];
    __nv_bfloat16 h0 = __float2bfloat16(v.x);
    __nv_bfloat16 h1 = __float2bfloat16(v.y);
    hi[i] = __halves2bfloat162(h0, h1);
    lo[i] = __halves2bfloat162(__float2bfloat16(v.x - __bfloat162float(h0)),
                               __float2bfloat16(v.y - __bfloat162float(h1)));
}

// ================= lam scalar =================
__global__ void lam_kernel(const float* __restrict__ lq1, const float* __restrict__ lk1,
                           const float* __restrict__ lq2, const float* __restrict__ lk2,
                           const int* __restrict__ lptr)
{
    __shared__ float r1[128], r2[128];
    int t = threadIdx.x;
    r1[t] = lq1[t]*lk1[t];
    r2[t] = lq2[t]*lk2[t];
    __syncthreads();
    for (int o = 64; o; o >>= 1) {
        if (t < o) { r1[t] += r1[t+o]; r2[t] += r2[t+o]; }
        __syncthreads();
    }
    if (t == 0) {
        float lam_init = 0.8f - 0.6f*expf(-0.3f*(float)lptr[0]);
        g_scal[0] = expf(r1[0]) - expf(r2[0]) + lam_init;
        g_scal[1] = 1.0f - lam_init;
    }
}

// ================= SIMT 64x64 GEMM tile (small w1/w2 GEMMs) =================
__device__ __forceinline__ void gemm_tile_64(
    const float* __restrict__ A, int lda,
    const float* __restrict__ Bm, int ldb,
    float* __restrict__ C, int ldc,
    int Kd, int m0, int n0)
{
    __shared__ __align__(16) float As[16][68];
    __shared__ __align__(16) float Bs[16][68];
    const int tid = threadIdx.x;
    const int tx = tid & 15, ty = tid >> 4;
    const int lr = tid >> 2;
    const int lc = (tid & 3) << 2;
    float acc[4][4] = {};
    const float* Ap = A + (size_t)(m0 + lr)*lda + lc;
    const float* Bp = Bm + (size_t)(n0 + lr)*ldb + lc;
    for (int k0 = 0; k0 < Kd; k0 += 16) {
        float4 av = *(const float4*)(Ap + k0);
        float4 bv = *(const float4*)(Bp + k0);
        As[lc+0][lr]=av.x; As[lc+1][lr]=av.y; As[lc+2][lr]=av.z; As[lc+3][lr]=av.w;
        Bs[lc+0][lr]=bv.x; Bs[lc+1][lr]=bv.y; Bs[lc+2][lr]=bv.z; Bs[lc+3][lr]=bv.w;
        __syncthreads();
#pragma unroll
        for (int kk = 0; kk < 16; ++kk) {
            float4 a = *(const float4*)&As[kk][ty<<2];
            float4 b = *(const float4*)&Bs[kk][tx<<2];
            acc[0][0] += a.x*b.x; acc[0][1] += a.x*b.y; acc[0][2] += a.x*b.z; acc[0][3] += a.x*b.w;
            acc[1][0] += a.y*b.x; acc[1][1] += a.y*b.y; acc[1][2] += a.y*b.z; acc[1][3] += a.y*b.w;
            acc[2][0] += a.z*b.x; acc[2][1] += a.z*b.y; acc[2][2] += a.z*b.z; acc[2][3] += a.z*b.w;
            acc[3][0] += a.w*b.x; acc[3][1] += a.w*b.y; acc[3][2] += a.w*b.z; acc[3][3] += a.w*b.w;
        }
        __syncthreads();
    }
#pragma unroll
    for (int i = 0; i < 4; i++) {
        float4 o;
        o.x = acc[i][0]; o.y = acc[i][1]; o.z = acc[i][2]; o.w = acc[i][3];
        *(float4*)(C + (size_t)(m0 + (ty<<2) + i)*ldc + n0 + (tx<<2)) = o;
    }
}

// w1[b,h,t,j]  = sum_d q[b,t,h*128+d] * sk[b,h,j,d]   (z = 0..5)
// w2t[b,h,t,j] = sum_d k[b,t,h*128+d] * sq[b,h,j,d]   (z = 6..11); heads 1..3 only
__global__ void __launch_bounds__(256) gemm_w()
{
    int z = blockIdx.z;
    int second = (z >= 6);
    int zz = second ? z - 6 : z;
    int b = zz / 3, h = zz % 3 + 1;
    const float* A  = (second ? g_k : g_q) + (size_t)b*Tv*NXv + h*HDv;
    const float* Bm = (second ? g_sq : g_sk) + (size_t)((b*4+h)*Lv)*HDv;
    float* C = (second ? g_w2t : g_w1) + (size_t)((b*4+h)*Tv)*Lv;
    gemm_tile_64(A, NXv, Bm, HDv, C, Lv, HDv, blockIdx.x*64, 0);
}

// ================= sq / sk gather + normalize + scale =================
__global__ void sqsk_kernel(const int* __restrict__ landmark,
                            const float* __restrict__ m1,
                            const float* __restrict__ m2)
{
    int idx = blockIdx.x;
    int which = idx & 1;
    int rest = idx >> 1;
    int j  = rest % Lv;
    int hm = (rest / Lv) % 3;
    int b  = rest / (Lv*3);
    int h  = hm + 1;
    int t  = threadIdx.x;
    int tok = landmark[j];
    const float* src = (which ? g_k : g_q) + (size_t)(b*Tv + tok)*NXv + h*HDv;
    float v = src[t];
    __shared__ float red[128];
    red[t] = v*v;
    __syncthreads();
    for (int o = 64; o; o >>= 1) { if (t < o) red[t] += red[t+o]; __syncthreads(); }
    float nrm = sqrtf(red[0]);
    float scale = (which ? m2[h*Lv + j] : m1[h*Lv + j]) / nrm;
    float* dst = (which ? g_sk : g_sq) + (size_t)((b*4+h)*Lv + j)*HDv;
    dst[t] = v * scale;
}

// ================= symmetric mask -> per-row CSR =================
__global__ void mask_kernel(const int* __restrict__ rns)
{
    int warp = (blockIdx.x * blockDim.x + threadIdx.x) >> 5;
    int lane = threadIdx.x & 31;
    int b = warp >> 11, i = warp & (Tv-1);
    const int* row = rns + (size_t)warp * KIv;
    int j = row[lane];
    bool dup = false;
#pragma unroll
    for (int k2 = 0; k2 < 32; ++k2) {
        int jj = __shfl_sync(0xffffffffu, j, k2);
        if (k2 < lane && jj == j) dup = true;
    }
    bool mem = false;
    const int* rj = rns + (size_t)(b*Tv + j)*KIv;
#pragma unroll
    for (int m = 0; m < 32; ++m) if (rj[m] == i) mem = true;
    bool valid = (!dup) && mem;
    unsigned bal = __ballot_sync(0xffffffffu, valid);
    if (valid) {
        int pos = __popc(bal & ((1u << lane) - 1u));
        g_cols[(size_t)warp*KIv + pos] = j;
    }
    if (lane == 0) g_cnt[warp] = __popc(bal);
}

// ================= column sum of v (zero-nnz rows) =================
__global__ void colsumA()
{
    int g = blockIdx.x*256 + threadIdx.x;
    int chunk = g >> 10;
    int c = g & 1023;
    int b = c >> 9, col = c & 511;
    const float* p = g_v + (size_t)(b*Tv + chunk*256)*NXv + col;
    float s = 0.f;
    for (int t = 0; t < 256; ++t) s += p[(size_t)t*NXv];
    g_vpart[g] = s;
}
__global__ void colsumB()
{
    int c = blockIdx.x*256 + threadIdx.x;
    float s = 0.f;
#pragma unroll
    for (int ch = 0; ch < 8; ++ch) s += g_vpart[ch*1024 + c];
    g_vcolsum[c] = s;
}

// ================= sparse attention rows + wmix + RMSNorm =================
__global__ void __launch_bounds__(256) attn_rows(const float* __restrict__ rms_g)
{
    const int r = blockIdx.x;
    const int b = r >> 11;
    const int i = r & (Tv-1);
    const int tid = threadIdx.x;
    __shared__ int   scols[KIv];
    __shared__ float sw[3][KIv];
    __shared__ float c0[KIv], c1[KIv];
    __shared__ float red[512];
    const int cnt = g_cnt[r];
    if (tid < KIv && tid < cnt) scols[tid] = g_cols[(size_t)r*KIv + tid];
    __syncthreads();
    const float lam = g_scal[0];
    const int wid = tid >> 5, lane = tid & 31;

    for (int task = wid; task < 3*cnt; task += 8) {
        int hm = task % 3, j = task / 3, h = hm + 1;
        const float* w1p = g_w1  + ((size_t)((b*4+h)*Tv + i)        << 6);
        const float* w2p = g_w2t + ((size_t)((b*4+h)*Tv + scols[j]) << 6);
        float s = w1p[lane]*w2p[lane] + w1p[lane+32]*w2p[lane+32];
#pragma unroll
        for (int o = 16; o; o >>= 1) s += __shfl_xor_sync(0xffffffffu, s, o);
        if (lane == 0) sw[hm][j] = s;
    }
    __syncthreads();

    if (wid == 0 && cnt > 0) {
        float p[3];
#pragma unroll
        for (int hm = 0; hm < 3; ++hm) {
            float x = (lane < cnt) ? sw[hm][lane] : -INFINITY;
            float mx = x;
#pragma unroll
            for (int o = 16; o; o >>= 1) mx = fmaxf(mx, __shfl_xor_sync(0xffffffffu, mx, o));
            float e = (lane < cnt) ? expf(x - mx) : 0.f;
            float sm = e;
#pragma unroll
            for (int o = 16; o; o >>= 1) sm += __shfl_xor_sync(0xffffffffu, sm, o);
            p[hm] = e / sm;
        }
        if (lane < cnt) {
            c0[lane] = (1.f - lam)*p[1] - lam*p[0];
            c1[lane] = p[1] - p[0] + (1.f - 2.f*lam)*p[2];
        }
    }
    __syncthreads();

    float s0 = 0.f, s1 = 0.f;
    if (cnt > 0) {
#pragma unroll 4
        for (int j = 0; j < cnt; ++j) {
            const float* vp = g_v + ((size_t)(b*Tv + scols[j]) << 9);
            s0 += c0[j] * vp[tid];
            s1 += c1[j] * vp[tid + 256];
        }
    } else {
        float u = (1.f - 2.f*lam) * (1.f/(float)Tv);
        s0 = u * g_vcolsum[b*NXv + tid];
        s1 = u * g_vcolsum[b*NXv + tid + 256];
    }

    red[tid]       = s0*s0;
    red[tid + 256] = s1*s1;
    __syncthreads();
#pragma unroll
    for (int o = 128; o; o >>= 1) {
        if (tid < o) { red[tid] += red[tid+o]; red[256+tid] += red[256+tid+o]; }
        __syncthreads();
    }
    float onem = g_scal[1];
    float g = rms_g[tid];
    float sc0 = rsqrtf(red[0]  *(1.f/256.f) + 1e-5f) * g * onem;
    float sc1 = rsqrtf(red[256]*(1.f/256.f) + 1e-5f) * g * onem;
    g_a[(size_t)r*NXv + tid]       = s0 * sc0;
    g_a[(size_t)r*NXv + 256 + tid] = s1 * sc1;
}

// ================= launch =================
extern "C" void kernel_launch(void* const* d_in, const int* in_sizes, int n_in,
                              void* d_out, int out_size)
{
    const float* x    = (const float*)d_in[0];
    const float* wq   = (const float*)d_in[1];
    const float* wk   = (const float*)d_in[2];
    const float* wv   = (const float*)d_in[3];
    const float* wo   = (const float*)d_in[4];
    const float* m1   = (const float*)d_in[5];
    const float* m2   = (const float*)d_in[6];
    const float* lq1  = (const float*)d_in[7];
    const float* lk1  = (const float*)d_in[8];
    const float* lq2  = (const float*)d_in[9];
    const float* lk2  = (const float*)d_in[10];
    const float* rmsg = (const float*)d_in[11];
    const int*   lp   = (const int*)d_in[12];
    const int*   rns  = (const int*)d_in[14];
    const int*   lmk  = (const int*)d_in[15];
    float* out = (float*)d_out;

    float *q, *k, *v, *a;
    cudaGetSymbolAddress((void**)&q, g_q);
    cudaGetSymbolAddress((void**)&k, g_k);
    cudaGetSymbolAddress((void**)&v, g_v);
    cudaGetSymbolAddress((void**)&a, g_a);
    __nv_bfloat16 *xh, *xl, *ah, *al, *wh, *wl;
    cudaGetSymbolAddress((void**)&xh, g_xh);
    cudaGetSymbolAddress((void**)&xl, g_xl);
    cudaGetSymbolAddress((void**)&ah, g_ah);
    cudaGetSymbolAddress((void**)&al, g_al);
    cudaGetSymbolAddress((void**)&wh, g_wh);
    cudaGetSymbolAddress((void**)&wl, g_wl);

    cudaFuncSetAttribute(gemm_mma, cudaFuncAttributeMaxDynamicSharedMemorySize, GEMM_SMEM_TOTAL);

    lam_kernel<<<1, 128>>>(lq1, lk1, lq2, lk2, lp);

    split_kernel<<<(Bv*Tv*NXv)/512, 256>>>((const float2*)x, (__nv_bfloat162*)xh, (__nv_bfloat162*)xl);
    const float* ws[4] = {wq, wk, wv, wo};
    for (int i = 0; i < 4; ++i)
        split_kernel<<<(NXv*NXv)/512, 256>>>((const float2*)ws[i],
            (__nv_bfloat162*)(wh + (size_t)i*NXv*NXv), (__nv_bfloat162*)(wl + (size_t)i*NXv*NXv));

    dim3 gg(Bv*Tv/128, NXv/128);
    gemm_mma<<<gg, 256, GEMM_SMEM_TOTAL>>>(xh, xl, wh + 0*NXv*NXv, wl + 0*NXv*NXv, q);
    gemm_mma<<<gg, 256, GEMM_SMEM_TOTAL>>>(xh, xl, wh + 1*NXv*NXv, wl + 1*NXv*NXv, k);
    gemm_mma<<<gg, 256, GEMM_SMEM_TOTAL>>>(xh, xl, wh + 2*NXv*NXv, wl + 2*NXv*NXv, v);

    sqsk_kernel<<<2*Bv*3*Lv, 128>>>(lmk, m1, m2);
    gemm_w<<<dim3(Tv/64, 1, 12), 256>>>();
    mask_kernel<<<Bv*Tv*32/256, 256>>>(rns);
    colsumA<<<32, 256>>>();
    colsumB<<<4, 256>>>();
    attn_rows<<<Bv*Tv, 256>>>(rmsg);

    split_kernel<<<(Bv*Tv*NXv)/512, 256>>>((const float2*)a, (__nv_bfloat162*)ah, (__nv_bfloat162*)al);
    gemm_mma<<<gg, 256, GEMM_SMEM_TOTAL>>>(ah, al, wh + 3*NXv*NXv, wl + 3*NXv*NXv, out);
}

// round 4
// speedup vs baseline: 2.4731x; 1.0959x over previous
#include <cuda_runtime.h>
#include <cuda_bf16.h>
#include <math.h>
#include <cstdint>

#define Bv 2
#define Tv 2048
#define NXv 512
#define HDv 128
#define Lv 64
#define KIv 32
#define NN (NXv*NXv)

// ================= scratch (device globals; no allocation allowed) =================
__device__ float g_q[Bv*Tv*NXv];
__device__ float g_k[Bv*Tv*NXv];
__device__ float g_v[Bv*Tv*NXv];
__device__ float g_sq[Bv*4*Lv*HDv];
__device__ float g_sk[Bv*4*Lv*HDv];
__device__ float g_w1 [Bv*4*Tv*Lv];
__device__ float g_w2t[Bv*4*Tv*Lv];
__device__ int   g_cols[Bv*Tv*KIv];
__device__ int   g_cnt [Bv*Tv];
__device__ float g_vpart[8*Bv*NXv];
__device__ float g_vcolsum[Bv*NXv];
__device__ float g_scal[2];
__device__ __nv_bfloat16 g_xh[Bv*Tv*NXv], g_xl[Bv*Tv*NXv];
__device__ __nv_bfloat16 g_ah[Bv*Tv*NXv], g_al[Bv*Tv*NXv];
__device__ __nv_bfloat16 g_wh[4*NN], g_wl[4*NN];

// ================= helpers =================
__device__ __forceinline__ uint32_t smem_u32(const void* p) {
    uint32_t a;
    asm("{ .reg .u64 t; cvta.to.shared.u64 t, %1; cvt.u32.u64 %0, t; }" : "=r"(a) : "l"(p));
    return a;
}
__device__ __forceinline__ uint32_t sw128(uint32_t off) { return off ^ ((off >> 3) & 0x70); }

#define CP16(dst, src)  asm volatile("cp.async.cg.shared.global [%0], [%1], 16;" :: "r"(dst), "l"(src) : "memory")
#define CP_COMMIT()     asm volatile("cp.async.commit_group;" ::: "memory")

#define LDSM4(r, a) \
    asm volatile("ldmatrix.sync.aligned.m8n8.x4.shared.b16 {%0,%1,%2,%3}, [%4];" \
        : "=r"((r)[0]), "=r"((r)[1]), "=r"((r)[2]), "=r"((r)[3]) : "r"(a))

#define MMA16816(d, a, b) \
    asm volatile("mma.sync.aligned.m16n8k16.row.col.f32.bf16.bf16.f32 " \
        "{%0,%1,%2,%3},{%4,%5,%6,%7},{%8,%9},{%0,%1,%2,%3};" \
        : "+f"((d)[0]), "+f"((d)[1]), "+f"((d)[2]), "+f"((d)[3]) \
        : "r"((a)[0]), "r"((a)[1]), "r"((a)[2]), "r"((a)[3]), "r"((b)[0]), "r"((b)[1]))

// ================= split-bf16 warp-MMA GEMM body ===============================
// Computes C[m0..m0+128, ncol0..ncol0+128] += A[m0.., :512] * Bslab[0..128, :512]^T
// A given as (Ah, Al); B slab pointers already offset to its first row.
// 256 threads; 2-stage cp.async pipeline; SW128 smem.
#define GEMM_SMEM_TOTAL (2*4*16384)

__device__ __forceinline__ void gemm_body(
    const __nv_bfloat16* __restrict__ Ah, const __nv_bfloat16* __restrict__ Al,
    const __nv_bfloat16* __restrict__ Bh, const __nv_bfloat16* __restrict__ Bl,
    float* __restrict__ C, int m0, int ncol0, char* smem)
{
    const uint32_t sb = smem_u32(smem);
    const int tid = threadIdx.x, wid = tid >> 5, lane = tid & 31;
    const int wm = wid & 1, wn = wid >> 1;

    float acc[4][4][4] = {};
    const __nv_bfloat16* bases[4] = {Ah, Al, Bh, Bl};

    auto load_stage = [&](int kc, uint32_t dstbase) {
#pragma unroll
        for (int t = 0; t < 4; ++t) {
            const int rb = (t < 2) ? m0 : 0;
#pragma unroll
            for (int j = 0; j < 4; ++j) {
                int idx = j * 256 + tid;
                int row = idx >> 3, c = idx & 7;
                const void* src = bases[t] + (size_t)(rb + row) * 512 + kc * 64 + c * 8;
                uint32_t dst = dstbase + t * 16384 + sw128((uint32_t)(row * 128 + c * 16));
                CP16(dst, src);
            }
        }
    };

    load_stage(0, sb);
    CP_COMMIT();

    for (int kc = 0; kc < 8; ++kc) {
        if (kc < 7) {
            load_stage(kc + 1, sb + ((kc + 1) & 1) * 65536);
            CP_COMMIT();
            asm volatile("cp.async.wait_group 1;" ::: "memory");
        } else {
            asm volatile("cp.async.wait_group 0;" ::: "memory");
        }
        __syncthreads();
        const uint32_t sbuf = sb + (kc & 1) * 65536;

#pragma unroll
        for (int kk = 0; kk < 4; ++kk) {
            const int klo = kk * 2;
            uint32_t ah[4][4], al[4][4], bh[4][2], bl[4][2];
            const int arow = ((lane >> 3) & 1) * 8 + (lane & 7);
            const int achk = klo + (lane >> 4);
#pragma unroll
            for (int f = 0; f < 4; ++f) {
                uint32_t off = sw128((uint32_t)((wm * 64 + f * 16 + arow) * 128 + achk * 16));
                LDSM4(ah[f], sbuf + off);
                LDSM4(al[f], sbuf + 16384 + off);
            }
            const int brow = (lane >> 4) * 8 + (lane & 7);
            const int bchk = klo + ((lane >> 3) & 1);
#pragma unroll
            for (int p = 0; p < 2; ++p) {
                uint32_t off = sw128((uint32_t)((wn * 32 + p * 16 + brow) * 128 + bchk * 16));
                uint32_t r[4];
                LDSM4(r, sbuf + 32768 + off);
                bh[2*p][0] = r[0]; bh[2*p][1] = r[1];
                bh[2*p+1][0] = r[2]; bh[2*p+1][1] = r[3];
                LDSM4(r, sbuf + 49152 + off);
                bl[2*p][0] = r[0]; bl[2*p][1] = r[1];
                bl[2*p+1][0] = r[2]; bl[2*p+1][1] = r[3];
            }
#pragma unroll
            for (int f = 0; f < 4; ++f)
#pragma unroll
                for (int n = 0; n < 4; ++n) {
                    MMA16816(acc[f][n], ah[f], bh[n]);
                    MMA16816(acc[f][n], ah[f], bl[n]);
                    MMA16816(acc[f][n], al[f], bh[n]);
                }
        }
        __syncthreads();
    }

    const int rbase = m0 + wm * 64 + (lane >> 2);
    const int cbase = ncol0 + wn * 32 + (lane & 3) * 2;
#pragma unroll
    for (int f = 0; f < 4; ++f)
#pragma unroll
        for (int n = 0; n < 4; ++n) {
            float* p0 = C + (size_t)(rbase + f * 16) * 512 + cbase + n * 8;
            *(float2*)p0 = make_float2(acc[f][n][0], acc[f][n][1]);
            *(float2*)(p0 + 8 * 512) = make_float2(acc[f][n][2], acc[f][n][3]);
        }
}

// Fused q/k/v projection. grid (32, 10):
//  y 0..2 : q cols 128..511 (wq rows 128..511)   [head 0 of q never read]
//  y 3..5 : k cols 128..511 (wk rows 128..511)
//  y 6..9 : v cols 0..511   (wv rows 0..511)
__global__ void __launch_bounds__(256) gemm_qkv()
{
    extern __shared__ char smem[];
    int y = blockIdx.y;
    int widx, brow;
    float* C;
    if (y < 3)      { widx = 0; brow = 128 + y * 128;      C = g_q; }
    else if (y < 6) { widx = 1; brow = 128 + (y - 3) * 128; C = g_k; }
    else            { widx = 2; brow = (y - 6) * 128;       C = g_v; }
    gemm_body(g_xh, g_xl,
              g_wh + (size_t)widx * NN + (size_t)brow * 512,
              g_wl + (size_t)widx * NN + (size_t)brow * 512,
              C, blockIdx.x * 128, brow, smem);
}

// Output projection: out = a @ wo^T. grid (32, 4).
__global__ void __launch_bounds__(256) gemm_out(float* __restrict__ out)
{
    extern __shared__ char smem[];
    int brow = blockIdx.y * 128;
    gemm_body(g_ah, g_al,
              g_wh + 3ull * NN + (size_t)brow * 512,
              g_wl + 3ull * NN + (size_t)brow * 512,
              out, blockIdx.x * 128, brow, smem);
}

// ================= fp32 -> (hi,lo) bf16 splits =================
__global__ void split_x(const float2* __restrict__ src)
{
    int i = blockIdx.x * 256 + threadIdx.x;
    float2 v = src[i];
    __nv_bfloat16 h0 = __float2bfloat16(v.x);
    __nv_bfloat16 h1 = __float2bfloat16(v.y);
    ((__nv_bfloat162*)g_xh)[i] = __halves2bfloat162(h0, h1);
    ((__nv_bfloat162*)g_xl)[i] = __halves2bfloat162(
        __float2bfloat16(v.x - __bfloat162float(h0)),
        __float2bfloat16(v.y - __bfloat162float(h1)));
}
// grid (512, 4): y selects which weight
__global__ void split_w(const float2* __restrict__ w0, const float2* __restrict__ w1,
                        const float2* __restrict__ w2, const float2* __restrict__ w3)
{
    const float2* src = (blockIdx.y == 0) ? w0 : (blockIdx.y == 1) ? w1 :
                        (blockIdx.y == 2) ? w2 : w3;
    int i = blockIdx.x * 256 + threadIdx.x;
    size_t o = (size_t)blockIdx.y * (NN/2) + i;
    float2 v = src[i];
    __nv_bfloat16 h0 = __float2bfloat16(v.x);
    __nv_bfloat16 h1 = __float2bfloat16(v.y);
    ((__nv_bfloat162*)g_wh)[o] = __halves2bfloat162(h0, h1);
    ((__nv_bfloat162*)g_wl)[o] = __halves2bfloat162(
        __float2bfloat16(v.x - __bfloat162float(h0)),
        __float2bfloat16(v.y - __bfloat162float(h1)));
}

// ================= lam scalar =================
__global__ void lam_kernel(const float* __restrict__ lq1, const float* __restrict__ lk1,
                           const float* __restrict__ lq2, const float* __restrict__ lk2,
                           const int* __restrict__ lptr)
{
    __shared__ float r1[128], r2[128];
    int t = threadIdx.x;
    r1[t] = lq1[t]*lk1[t];
    r2[t] = lq2[t]*lk2[t];
    __syncthreads();
    for (int o = 64; o; o >>= 1) {
        if (t < o) { r1[t] += r1[t+o]; r2[t] += r2[t+o]; }
        __syncthreads();
    }
    if (t == 0) {
        float lam_init = 0.8f - 0.6f*expf(-0.3f*(float)lptr[0]);
        g_scal[0] = expf(r1[0]) - expf(r2[0]) + lam_init;
        g_scal[1] = 1.0f - lam_init;
    }
}

// ================= SIMT 64x64 GEMM tile (small w1/w2 GEMMs) =================
__device__ __forceinline__ void gemm_tile_64(
    const float* __restrict__ A, int lda,
    const float* __restrict__ Bm, int ldb,
    float* __restrict__ C, int ldc,
    int Kd, int m0, int n0)
{
    __shared__ __align__(16) float As[16][68];
    __shared__ __align__(16) float Bs[16][68];
    const int tid = threadIdx.x;
    const int tx = tid & 15, ty = tid >> 4;
    const int lr = tid >> 2;
    const int lc = (tid & 3) << 2;
    float acc[4][4] = {};
    const float* Ap = A + (size_t)(m0 + lr)*lda + lc;
    const float* Bp = Bm + (size_t)(n0 + lr)*ldb + lc;
    for (int k0 = 0; k0 < Kd; k0 += 16) {
        float4 av = *(const float4*)(Ap + k0);
        float4 bv = *(const float4*)(Bp + k0);
        As[lc+0][lr]=av.x; As[lc+1][lr]=av.y; As[lc+2][lr]=av.z; As[lc+3][lr]=av.w;
        Bs[lc+0][lr]=bv.x; Bs[lc+1][lr]=bv.y; Bs[lc+2][lr]=bv.z; Bs[lc+3][lr]=bv.w;
        __syncthreads();
#pragma unroll
        for (int kk = 0; kk < 16; ++kk) {
            float4 a = *(const float4*)&As[kk][ty<<2];
            float4 b = *(const float4*)&Bs[kk][tx<<2];
            acc[0][0] += a.x*b.x; acc[0][1] += a.x*b.y; acc[0][2] += a.x*b.z; acc[0][3] += a.x*b.w;
            acc[1][0] += a.y*b.x; acc[1][1] += a.y*b.y; acc[1][2] += a.y*b.z; acc[1][3] += a.y*b.w;
            acc[2][0] += a.z*b.x; acc[2][1] += a.z*b.y; acc[2][2] += a.z*b.z; acc[2][3] += a.z*b.w;
            acc[3][0] += a.w*b.x; acc[3][1] += a.w*b.y; acc[3][2] += a.w*b.z; acc[3][3] += a.w*b.w;
        }
        __syncthreads();
    }
#pragma unroll
    for (int i = 0; i < 4; i++) {
        float4 o;
        o.x = acc[i][0]; o.y = acc[i][1]; o.z = acc[i][2]; o.w = acc[i][3];
        *(float4*)(C + (size_t)(m0 + (ty<<2) + i)*ldc + n0 + (tx<<2)) = o;
    }
}

// w1[b,h,t,j]  = sum_d q[b,t,h*128+d] * sk[b,h,j,d]   (z = 0..5)
// w2t[b,h,t,j] = sum_d k[b,t,h*128+d] * sq[b,h,j,d]   (z = 6..11); heads 1..3 only
__global__ void __launch_bounds__(256) gemm_w()
{
    int z = blockIdx.z;
    int second = (z >= 6);
    int zz = second ? z - 6 : z;
    int b = zz / 3, h = zz % 3 + 1;
    const float* A  = (second ? g_k : g_q) + (size_t)b*Tv*NXv + h*HDv;
    const float* Bm = (second ? g_sq : g_sk) + (size_t)((b*4+h)*Lv)*HDv;
    float* C = (second ? g_w2t : g_w1) + (size_t)((b*4+h)*Tv)*Lv;
    gemm_tile_64(A, NXv, Bm, HDv, C, Lv, HDv, blockIdx.x*64, 0);
}

// ================= sq / sk gather + normalize + scale =================
__global__ void sqsk_kernel(const int* __restrict__ landmark,
                            const float* __restrict__ m1,
                            const float* __restrict__ m2)
{
    int idx = blockIdx.x;
    int which = idx & 1;
    int rest = idx >> 1;
    int j  = rest % Lv;
    int hm = (rest / Lv) % 3;
    int b  = rest / (Lv*3);
    int h  = hm + 1;
    int t  = threadIdx.x;
    int tok = landmark[j];
    const float* src = (which ? g_k : g_q) + (size_t)(b*Tv + tok)*NXv + h*HDv;
    float v = src[t];
    __shared__ float red[128];
    red[t] = v*v;
    __syncthreads();
    for (int o = 64; o; o >>= 1) { if (t < o) red[t] += red[t+o]; __syncthreads(); }
    float nrm = sqrtf(red[0]);
    float scale = (which ? m2[h*Lv + j] : m1[h*Lv + j]) / nrm;
    float* dst = (which ? g_sk : g_sq) + (size_t)((b*4+h)*Lv + j)*HDv;
    dst[t] = v * scale;
}

// ================= symmetric mask -> per-row CSR =================
__global__ void mask_kernel(const int* __restrict__ rns)
{
    int warp = (blockIdx.x * blockDim.x + threadIdx.x) >> 5;
    int lane = threadIdx.x & 31;
    int b = warp >> 11, i = warp & (Tv-1);
    const int* row = rns + (size_t)warp * KIv;
    int j = row[lane];
    bool dup = false;
#pragma unroll
    for (int k2 = 0; k2 < 32; ++k2) {
        int jj = __shfl_sync(0xffffffffu, j, k2);
        if (k2 < lane && jj == j) dup = true;
    }
    bool mem = false;
    const int* rj = rns + (size_t)(b*Tv + j)*KIv;
#pragma unroll
    for (int m = 0; m < 32; ++m) if (rj[m] == i) mem = true;
    bool valid = (!dup) && mem;
    unsigned bal = __ballot_sync(0xffffffffu, valid);
    if (valid) {
        int pos = __popc(bal & ((1u << lane) - 1u));
        g_cols[(size_t)warp*KIv + pos] = j;
    }
    if (lane == 0) g_cnt[warp] = __popc(bal);
}

// ================= column sum of v (zero-nnz rows) =================
__global__ void colsumA()
{
    int g = blockIdx.x*256 + threadIdx.x;
    int chunk = g >> 10;
    int c = g & 1023;
    int b = c >> 9, col = c & 511;
    const float* p = g_v + (size_t)(b*Tv + chunk*256)*NXv + col;
    float s = 0.f;
    for (int t = 0; t < 256; ++t) s += p[(size_t)t*NXv];
    g_vpart[g] = s;
}
__global__ void colsumB()
{
    int c = blockIdx.x*256 + threadIdx.x;
    float s = 0.f;
#pragma unroll
    for (int ch = 0; ch < 8; ++ch) s += g_vpart[ch*1024 + c];
    g_vcolsum[c] = s;
}

// ================= sparse attention rows + wmix + RMSNorm + bf16 split ===========
__global__ void __launch_bounds__(256) attn_rows(const float* __restrict__ rms_g)
{
    const int r = blockIdx.x;
    const int b = r >> 11;
    const int i = r & (Tv-1);
    const int tid = threadIdx.x;
    __shared__ int   scols[KIv];
    __shared__ float sw[3][KIv];
    __shared__ float c0[KIv], c1[KIv];
    __shared__ float red[512];
    const int cnt = g_cnt[r];
    if (tid < KIv && tid < cnt) scols[tid] = g_cols[(size_t)r*KIv + tid];
    __syncthreads();
    const float lam = g_scal[0];
    const int wid = tid >> 5, lane = tid & 31;

    for (int task = wid; task < 3*cnt; task += 8) {
        int hm = task % 3, j = task / 3, h = hm + 1;
        const float* w1p = g_w1  + ((size_t)((b*4+h)*Tv + i)        << 6);
        const float* w2p = g_w2t + ((size_t)((b*4+h)*Tv + scols[j]) << 6);
        float s = w1p[lane]*w2p[lane] + w1p[lane+32]*w2p[lane+32];
#pragma unroll
        for (int o = 16; o; o >>= 1) s += __shfl_xor_sync(0xffffffffu, s, o);
        if (lane == 0) sw[hm][j] = s;
    }
    __syncthreads();

    if (wid == 0 && cnt > 0) {
        float p[3];
#pragma unroll
        for (int hm = 0; hm < 3; ++hm) {
            float x = (lane < cnt) ? sw[hm][lane] : -INFINITY;
            float mx = x;
#pragma unroll
            for (int o = 16; o; o >>= 1) mx = fmaxf(mx, __shfl_xor_sync(0xffffffffu, mx, o));
            float e = (lane < cnt) ? expf(x - mx) : 0.f;
            float sm = e;
#pragma unroll
            for (int o = 16; o; o >>= 1) sm += __shfl_xor_sync(0xffffffffu, sm, o);
            p[hm] = e / sm;
        }
        if (lane < cnt) {
            c0[lane] = (1.f - lam)*p[1] - lam*p[0];
            c1[lane] = p[1] - p[0] + (1.f - 2.f*lam)*p[2];
        }
    }
    __syncthreads();

    float s0 = 0.f, s1 = 0.f;
    if (cnt > 0) {
#pragma unroll 4
        for (int j = 0; j < cnt; ++j) {
            const float* vp = g_v + ((size_t)(b*Tv + scols[j]) << 9);
            s0 += c0[j] * vp[tid];
            s1 += c1[j] * vp[tid + 256];
        }
    } else {
        float u = (1.f - 2.f*lam) * (1.f/(float)Tv);
        s0 = u * g_vcolsum[b*NXv + tid];
        s1 = u * g_vcolsum[b*NXv + tid + 256];
    }

    red[tid]       = s0*s0;
    red[tid + 256] = s1*s1;
    __syncthreads();
#pragma unroll
    for (int o = 128; o; o >>= 1) {
        if (tid < o) { red[tid] += red[tid+o]; red[256+tid] += red[256+tid+o]; }
        __syncthreads();
    }
    float onem = g_scal[1];
    float g = rms_g[tid];
    float a0 = s0 * rsqrtf(red[0]  *(1.f/256.f) + 1e-5f) * g * onem;
    float a1 = s1 * rsqrtf(red[256]*(1.f/256.f) + 1e-5f) * g * onem;
    // split to bf16 (hi, lo) directly — feeds gemm_out
    __nv_bfloat16 h0 = __float2bfloat16(a0);
    __nv_bfloat16 h1 = __float2bfloat16(a1);
    size_t o0 = (size_t)r*NXv + tid, o1 = o0 + 256;
    g_ah[o0] = h0;                                   g_ah[o1] = h1;
    g_al[o0] = __float2bfloat16(a0 - __bfloat162float(h0));
    g_al[o1] = __float2bfloat16(a1 - __bfloat162float(h1));
}

// ================= launch =================
extern "C" void kernel_launch(void* const* d_in, const int* in_sizes, int n_in,
                              void* d_out, int out_size)
{
    const float* x    = (const float*)d_in[0];
    const float* wq   = (const float*)d_in[1];
    const float* wk   = (const float*)d_in[2];
    const float* wv   = (const float*)d_in[3];
    const float* wo   = (const float*)d_in[4];
    const float* m1   = (const float*)d_in[5];
    const float* m2   = (const float*)d_in[6];
    const float* lq1  = (const float*)d_in[7];
    const float* lk1  = (const float*)d_in[8];
    const float* lq2  = (const float*)d_in[9];
    const float* lk2  = (const float*)d_in[10];
    const float* rmsg = (const float*)d_in[11];
    const int*   lp   = (const int*)d_in[12];
    const int*   rns  = (const int*)d_in[14];
    const int*   lmk  = (const int*)d_in[15];
    float* out = (float*)d_out;

    cudaFuncSetAttribute(gemm_qkv, cudaFuncAttributeMaxDynamicSharedMemorySize, GEMM_SMEM_TOTAL);
    cudaFuncSetAttribute(gemm_out, cudaFuncAttributeMaxDynamicSharedMemorySize, GEMM_SMEM_TOTAL);

    lam_kernel<<<1, 128>>>(lq1, lk1, lq2, lk2, lp);
    split_x<<<(Bv*Tv*NXv)/512, 256>>>((const float2*)x);
    split_w<<<dim3(NN/512, 4), 256>>>((const float2*)wq, (const float2*)wk,
                                      (const float2*)wv, (const float2*)wo);

    gemm_qkv<<<dim3(Bv*Tv/128, 10), 256, GEMM_SMEM_TOTAL>>>();

    sqsk_kernel<<<2*Bv*3*Lv, 128>>>(lmk, m1, m2);
    gemm_w<<<dim3(Tv/64, 1, 12), 256>>>();
    mask_kernel<<<Bv*Tv*32/256, 256>>>(rns);
    colsumA<<<32, 256>>>();
    colsumB<<<4, 256>>>();
    attn_rows<<<Bv*Tv, 256>>>(rmsg);

    gemm_out<<<dim3(Bv*Tv/128, 4), 256, GEMM_SMEM_TOTAL>>>(out);
}

// round 5
// speedup vs baseline: 2.5501x; 1.0312x over previous
#include <cuda_runtime.h>
#include <cuda_bf16.h>
#include <math.h>
#include <cstdint>

#define Bv 2
#define Tv 2048
#define NXv 512
#define HDv 128
#define Lv 64
#define KIv 32
#define NN (NXv*NXv)
#define QKW 384   // pruned q/k width (heads 1..3)

// ================= scratch (device globals; no allocation allowed) =================
__device__ float g_v[Bv*Tv*NXv];
__device__ float g_w1 [Bv*4*Tv*Lv];
__device__ float g_w2t[Bv*4*Tv*Lv];
__device__ int   g_cols[Bv*Tv*KIv];
__device__ int   g_cnt [Bv*Tv];
__device__ float g_vpart[8*Bv*NXv];
__device__ float g_vcolsum[Bv*NXv];
__device__ float g_scal[2];
__device__ __nv_bfloat16 g_xh[Bv*Tv*NXv], g_xl[Bv*Tv*NXv];
__device__ __nv_bfloat16 g_ah[Bv*Tv*NXv], g_al[Bv*Tv*NXv];
__device__ __nv_bfloat16 g_wh[4*NN], g_wl[4*NN];
__device__ __nv_bfloat16 g_qh[Bv*Tv*QKW], g_ql[Bv*Tv*QKW];
__device__ __nv_bfloat16 g_kh[Bv*Tv*QKW], g_kl[Bv*Tv*QKW];
__device__ __nv_bfloat16 g_skh[Bv*3*Lv*HDv], g_skl[Bv*3*Lv*HDv];
__device__ __nv_bfloat16 g_sqh[Bv*3*Lv*HDv], g_sql[Bv*3*Lv*HDv];

// ================= helpers =================
__device__ __forceinline__ uint32_t smem_u32(const void* p) {
    uint32_t a;
    asm("{ .reg .u64 t; cvta.to.shared.u64 t, %1; cvt.u32.u64 %0, t; }" : "=r"(a) : "l"(p));
    return a;
}
__device__ __forceinline__ uint32_t sw128(uint32_t off) { return off ^ ((off >> 3) & 0x70); }

#define CP16(dst, src)  asm volatile("cp.async.cg.shared.global [%0], [%1], 16;" :: "r"(dst), "l"(src) : "memory")
#define CP_COMMIT()     asm volatile("cp.async.commit_group;" ::: "memory")

#define LDSM4(r, a) \
    asm volatile("ldmatrix.sync.aligned.m8n8.x4.shared.b16 {%0,%1,%2,%3}, [%4];" \
        : "=r"((r)[0]), "=r"((r)[1]), "=r"((r)[2]), "=r"((r)[3]) : "r"(a))

#define MMA16816(d, a, b) \
    asm volatile("mma.sync.aligned.m16n8k16.row.col.f32.bf16.bf16.f32 " \
        "{%0,%1,%2,%3},{%4,%5,%6,%7},{%8,%9},{%0,%1,%2,%3};" \
        : "+f"((d)[0]), "+f"((d)[1]), "+f"((d)[2]), "+f"((d)3 == 3 ? (d)[3] : (d)[3])); // placeholder

#undef MMA16816
#define MMA16816(d, a, b) \
    asm volatile("mma.sync.aligned.m16n8k16.row.col.f32.bf16.bf16.f32 " \
        "{%0,%1,%2,%3},{%4,%5,%6,%7},{%8,%9},{%0,%1,%2,%3};" \
        : "+f"((d)[0]), "+f"((d)[1]), "+f"((d)[2]), "+f"((d)[3]) \
        : "r"((a)[0]), "r"((a)[1]), "r"((a)[2]), "r"((a)[3]), "r"((b)[0]), "r"((b)[1]))

// ================= 512-thread split-bf16 MMA mainloop: 128x128 tile, K=512 =========
// Warp grid 4x4, warp tile 32x32. smem: 2 stages x 4 tiles x 16KB = 128KB.
#define GEMM_SMEM_TOTAL (2*4*16384)

__device__ __forceinline__ void mainloop512(
    const __nv_bfloat16* __restrict__ Ah, const __nv_bfloat16* __restrict__ Al,
    const __nv_bfloat16* __restrict__ Bh, const __nv_bfloat16* __restrict__ Bl,
    int m0, char* smem, float acc[2][4][4])
{
    const uint32_t sb = smem_u32(smem);
    const int tid = threadIdx.x, lane = tid & 31;
    const int wm = (tid >> 5) & 3, wn = tid >> 7;
    const __nv_bfloat16* bases[4] = {Ah, Al, Bh, Bl};

    auto load_stage = [&](int kc, uint32_t dstbase) {
#pragma unroll
        for (int t = 0; t < 4; ++t) {
            const int rb = (t < 2) ? m0 : 0;
#pragma unroll
            for (int j = 0; j < 2; ++j) {
                int idx = j * 512 + tid;          // 0..1023
                int row = idx >> 3, c = idx & 7;
                const void* src = bases[t] + (size_t)(rb + row) * 512 + kc * 64 + c * 8;
                uint32_t dst = dstbase + t * 16384 + sw128((uint32_t)(row * 128 + c * 16));
                CP16(dst, src);
            }
        }
    };

    load_stage(0, sb);
    CP_COMMIT();

    for (int kc = 0; kc < 8; ++kc) {
        if (kc < 7) {
            load_stage(kc + 1, sb + ((kc + 1) & 1) * 65536);
            CP_COMMIT();
            asm volatile("cp.async.wait_group 1;" ::: "memory");
        } else {
            asm volatile("cp.async.wait_group 0;" ::: "memory");
        }
        __syncthreads();
        const uint32_t sbuf = sb + (kc & 1) * 65536;

#pragma unroll
        for (int kk = 0; kk < 4; ++kk) {
            const int klo = kk * 2;
            uint32_t ah[2][4], al[2][4], bh[4][2], bl[4][2];
            const int arow = ((lane >> 3) & 1) * 8 + (lane & 7);
            const int achk = klo + (lane >> 4);
#pragma unroll
            for (int f = 0; f < 2; ++f) {
                uint32_t off = sw128((uint32_t)((wm * 32 + f * 16 + arow) * 128 + achk * 16));
                LDSM4(ah[f], sbuf + off);
                LDSM4(al[f], sbuf + 16384 + off);
            }
            const int brow = (lane >> 4) * 8 + (lane & 7);
            const int bchk = klo + ((lane >> 3) & 1);
#pragma unroll
            for (int p = 0; p < 2; ++p) {
                uint32_t off = sw128((uint32_t)((wn * 32 + p * 16 + brow) * 128 + bchk * 16));
                uint32_t r[4];
                LDSM4(r, sbuf + 32768 + off);
                bh[2*p][0] = r[0]; bh[2*p][1] = r[1];
                bh[2*p+1][0] = r[2]; bh[2*p+1][1] = r[3];
                LDSM4(r, sbuf + 49152 + off);
                bl[2*p][0] = r[0]; bl[2*p][1] = r[1];
                bl[2*p+1][0] = r[2]; bl[2*p+1][1] = r[3];
            }
#pragma unroll
            for (int f = 0; f < 2; ++f)
#pragma unroll
                for (int n = 0; n < 4; ++n) {
                    MMA16816(acc[f][n], ah[f], bh[n]);
                    MMA16816(acc[f][n], ah[f], bl[n]);
                    MMA16816(acc[f][n], al[f], bh[n]);
                }
        }
        __syncthreads();
    }
}

// Fused q/k/v projection. grid (32, 10):
//  y 0..2 : q cols 128..511 -> bf16 (hi,lo) pruned [4096, 384]
//  y 3..5 : k cols 128..511 -> bf16 (hi,lo) pruned
//  y 6..9 : v cols 0..511   -> fp32
__global__ void __launch_bounds__(512) gemm_qkv()
{
    extern __shared__ char smem[];
    const int y = blockIdx.y;
    int widx, brow;
    if (y < 3)      { widx = 0; brow = 128 + y * 128; }
    else if (y < 6) { widx = 1; brow = 128 + (y - 3) * 128; }
    else            { widx = 2; brow = (y - 6) * 128; }
    const int m0 = blockIdx.x * 128;

    float acc[2][4][4] = {};
    mainloop512(g_xh, g_xl,
                g_wh + (size_t)widx * NN + (size_t)brow * 512,
                g_wl + (size_t)widx * NN + (size_t)brow * 512,
                m0, smem, acc);

    const int tid = threadIdx.x, lane = tid & 31;
    const int wm = (tid >> 5) & 3, wn = tid >> 7;
    const int r0 = m0 + wm * 32 + (lane >> 2);
    const int c0 = wn * 32 + (lane & 3) * 2;

    if (y < 6) {
        __nv_bfloat16* dh = widx ? g_kh : g_qh;
        __nv_bfloat16* dl = widx ? g_kl : g_ql;
        const int cp0 = (brow - 128) + c0;
#pragma unroll
        for (int f = 0; f < 2; ++f)
#pragma unroll
            for (int n = 0; n < 4; ++n) {
#pragma unroll
                for (int hr = 0; hr < 2; ++hr) {
                    const int row = r0 + f * 16 + hr * 8;
                    float v0 = acc[f][n][hr*2], v1 = acc[f][n][hr*2+1];
                    __nv_bfloat16 h0 = __float2bfloat16(v0), h1 = __float2bfloat16(v1);
                    size_t o = (size_t)row * QKW + cp0 + n * 8;
                    *(__nv_bfloat162*)(dh + o) = __halves2bfloat162(h0, h1);
                    *(__nv_bfloat162*)(dl + o) = __halves2bfloat162(
                        __float2bfloat16(v0 - __bfloat162float(h0)),
                        __float2bfloat16(v1 - __bfloat162float(h1)));
                }
            }
    } else {
#pragma unroll
        for (int f = 0; f < 2; ++f)
#pragma unroll
            for (int n = 0; n < 4; ++n) {
                float* p0 = g_v + (size_t)(r0 + f * 16) * 512 + brow + c0 + n * 8;
                *(float2*)p0 = make_float2(acc[f][n][0], acc[f][n][1]);
                *(float2*)(p0 + 8 * 512) = make_float2(acc[f][n][2], acc[f][n][3]);
            }
    }
}

// Output projection: out = a @ wo^T. grid (32, 4).
__global__ void __launch_bounds__(512) gemm_out(float* __restrict__ out)
{
    extern __shared__ char smem[];
    const int brow = blockIdx.y * 128;
    const int m0 = blockIdx.x * 128;
    float acc[2][4][4] = {};
    mainloop512(g_ah, g_al,
                g_wh + 3ull * NN + (size_t)brow * 512,
                g_wl + 3ull * NN + (size_t)brow * 512,
                m0, smem, acc);
    const int tid = threadIdx.x, lane = tid & 31;
    const int wm = (tid >> 5) & 3, wn = tid >> 7;
    const int r0 = m0 + wm * 32 + (lane >> 2);
    const int c0 = brow + wn * 32 + (lane & 3) * 2;
#pragma unroll
    for (int f = 0; f < 2; ++f)
#pragma unroll
        for (int n = 0; n < 4; ++n) {
            float* p0 = out + (size_t)(r0 + f * 16) * 512 + c0 + n * 8;
            *(float2*)p0 = make_float2(acc[f][n][0], acc[f][n][1]);
            *(float2*)(p0 + 8 * 512) = make_float2(acc[f][n][2], acc[f][n][3]);
        }
}

// ================= gemm_w via MMA: w1 = q.sk^T, w2t = k.sq^T ======================
// C[128,64] per CTA; A [4096, 384] bf16 pruned, K=128 (head dim); B [64, 128].
// grid (16, 6, 2): x = t-tile, y = b*3+hm, z = second. 256 threads, warp grid 4x2.
#define GW_SMEM (2*49152)
__global__ void __launch_bounds__(256) gemm_w_mma()
{
    extern __shared__ char smem[];
    const uint32_t sb = smem_u32(smem);
    const int tid = threadIdx.x, lane = tid & 31;
    const int wm = (tid >> 5) & 3, wn = tid >> 7;
    const int second = blockIdx.z;
    const int bh = blockIdx.y;
    const int b = bh / 3, hm = bh % 3;
    const int m0 = blockIdx.x * 128;

    const __nv_bfloat16* Ah = (second ? g_kh : g_qh) + (size_t)b*Tv*QKW + hm*HDv;
    const __nv_bfloat16* Al = (second ? g_kl : g_ql) + (size_t)b*Tv*QKW + hm*HDv;
    const __nv_bfloat16* Bh = (second ? g_sqh : g_skh) + (size_t)bh*Lv*HDv;
    const __nv_bfloat16* Bl = (second ? g_sql : g_skl) + (size_t)bh*Lv*HDv;
    float* C = (second ? g_w2t : g_w1) + ((size_t)((b*4+hm+1)*Tv) + m0) * Lv;

    float acc[2][4][4] = {};

    auto load_stage = [&](int kc, uint32_t dstb) {
#pragma unroll
        for (int t = 0; t < 2; ++t) {
            const __nv_bfloat16* base = t ? Al : Ah;
#pragma unroll
            for (int j = 0; j < 4; ++j) {
                int idx = j * 256 + tid;         // 0..1023
                int row = idx >> 3, c = idx & 7;
                const void* src = base + (size_t)(m0 + row) * QKW + kc * 64 + c * 8;
                uint32_t dst = dstb + t * 16384 + sw128((uint32_t)(row * 128 + c * 16));
                CP16(dst, src);
            }
        }
#pragma unroll
        for (int t = 0; t < 2; ++t) {
            const __nv_bfloat16* base = t ? Bl : Bh;
#pragma unroll
            for (int j = 0; j < 2; ++j) {
                int idx = j * 256 + tid;         // 0..511
                int row = idx >> 3, c = idx & 7;
                const void* src = base + (size_t)row * HDv + kc * 64 + c * 8;
                uint32_t dst = dstb + 32768 + t * 8192 + sw128((uint32_t)(row * 128 + c * 16));
                CP16(dst, src);
            }
        }
    };

    load_stage(0, sb); CP_COMMIT();
    load_stage(1, sb + 49152); CP_COMMIT();

    for (int kc = 0; kc < 2; ++kc) {
        if (kc == 0) asm volatile("cp.async.wait_group 1;" ::: "memory");
        else         asm volatile("cp.async.wait_group 0;" ::: "memory");
        __syncthreads();
        const uint32_t sbuf = sb + kc * 49152;
#pragma unroll
        for (int kk = 0; kk < 4; ++kk) {
            const int klo = kk * 2;
            uint32_t ah[2][4], al[2][4], bh[4][2], bl[4][2];
            const int arow = ((lane >> 3) & 1) * 8 + (lane & 7);
            const int achk = klo + (lane >> 4);
#pragma unroll
            for (int f = 0; f < 2; ++f) {
                uint32_t off = sw128((uint32_t)((wm * 32 + f * 16 + arow) * 128 + achk * 16));
                LDSM4(ah[f], sbuf + off);
                LDSM4(al[f], sbuf + 16384 + off);
            }
            const int brow = (lane >> 4) * 8 + (lane & 7);
            const int bchk = klo + ((lane >> 3) & 1);
#pragma unroll
            for (int p = 0; p < 2; ++p) {
                uint32_t off = sw128((uint32_t)((wn * 32 + p * 16 + brow) * 128 + bchk * 16));
                uint32_t r[4];
                LDSM4(r, sbuf + 32768 + off);
                bh[2*p][0] = r[0]; bh[2*p][1] = r[1];
                bh[2*p+1][0] = r[2]; bh[2*p+1][1] = r[3];
                LDSM4(r, sbuf + 40960 + off);
                bl[2*p][0] = r[0]; bl[2*p][1] = r[1];
                bl[2*p+1][0] = r[2]; bl[2*p+1][1] = r[3];
            }
#pragma unroll
            for (int f = 0; f < 2; ++f)
#pragma unroll
                for (int n = 0; n < 4; ++n) {
                    MMA16816(acc[f][n], ah[f], bh[n]);
                    MMA16816(acc[f][n], ah[f], bl[n]);
                    MMA16816(acc[f][n], al[f], bh[n]);
                }
        }
        __syncthreads();
    }

    const int r0 = wm * 32 + (lane >> 2);
    const int c0 = wn * 32 + (lane & 3) * 2;
#pragma unroll
    for (int f = 0; f < 2; ++f)
#pragma unroll
        for (int n = 0; n < 4; ++n) {
            float* p0 = C + (size_t)(r0 + f * 16) * Lv + c0 + n * 8;
            *(float2*)p0 = make_float2(acc[f][n][0], acc[f][n][1]);
            *(float2*)(p0 + 8 * Lv) = make_float2(acc[f][n][2], acc[f][n][3]);
        }
}

// ================= fp32 -> (hi,lo) bf16 splits =================
__global__ void split_x(const float2* __restrict__ src)
{
    int i = blockIdx.x * 256 + threadIdx.x;
    float2 v = src[i];
    __nv_bfloat16 h0 = __float2bfloat16(v.x);
    __nv_bfloat16 h1 = __float2bfloat16(v.y);
    ((__nv_bfloat162*)g_xh)[i] = __halves2bfloat162(h0, h1);
    ((__nv_bfloat162*)g_xl)[i] = __halves2bfloat162(
        __float2bfloat16(v.x - __bfloat162float(h0)),
        __float2bfloat16(v.y - __bfloat162float(h1)));
}
__global__ void split_w(const float2* __restrict__ w0, const float2* __restrict__ w1,
                        const float2* __restrict__ w2, const float2* __restrict__ w3)
{
    const float2* src = (blockIdx.y == 0) ? w0 : (blockIdx.y == 1) ? w1 :
                        (blockIdx.y == 2) ? w2 : w3;
    int i = blockIdx.x * 256 + threadIdx.x;
    size_t o = (size_t)blockIdx.y * (NN/2) + i;
    float2 v = src[i];
    __nv_bfloat16 h0 = __float2bfloat16(v.x);
    __nv_bfloat16 h1 = __float2bfloat16(v.y);
    ((__nv_bfloat162*)g_wh)[o] = __halves2bfloat162(h0, h1);
    ((__nv_bfloat162*)g_wl)[o] = __halves2bfloat162(
        __float2bfloat16(v.x - __bfloat162float(h0)),
        __float2bfloat16(v.y - __bfloat162float(h1)));
}

// ================= lam scalar =================
__global__ void lam_kernel(const float* __restrict__ lq1, const float* __restrict__ lk1,
                           const float* __restrict__ lq2, const float* __restrict__ lk2,
                           const int* __restrict__ lptr)
{
    __shared__ float r1[128], r2[128];
    int t = threadIdx.x;
    r1[t] = lq1[t]*lk1[t];
    r2[t] = lq2[t]*lk2[t];
    __syncthreads();
    for (int o = 64; o; o >>= 1) {
        if (t < o) { r1[t] += r1[t+o]; r2[t] += r2[t+o]; }
        __syncthreads();
    }
    if (t == 0) {
        float lam_init = 0.8f - 0.6f*expf(-0.3f*(float)lptr[0]);
        g_scal[0] = expf(r1[0]) - expf(r2[0]) + lam_init;
        g_scal[1] = 1.0f - lam_init;
    }
}

// ================= sq / sk: reconstruct, normalize, scale, re-split ==============
__global__ void sqsk_kernel(const int* __restrict__ landmark,
                            const float* __restrict__ m1,
                            const float* __restrict__ m2)
{
    int idx = blockIdx.x;
    int which = idx & 1;            // 0: sq (from q, m1)  1: sk (from k, m2)
    int rest = idx >> 1;
    int j  = rest % Lv;
    int hm = (rest / Lv) % 3;
    int b  = rest / (Lv*3);
    int t  = threadIdx.x;           // 0..127
    int tok = landmark[j];
    size_t off = (size_t)(b*Tv + tok)*QKW + hm*HDv + t;
    float v = which
        ? (__bfloat162float(g_kh[off]) + __bfloat162float(g_kl[off]))
        : (__bfloat162float(g_qh[off]) + __bfloat162float(g_ql[off]));
    __shared__ float red[128];
    red[t] = v*v;
    __syncthreads();
    for (int o = 64; o; o >>= 1) { if (t < o) red[t] += red[t+o]; __syncthreads(); }
    float scale = (which ? m2[(hm+1)*Lv + j] : m1[(hm+1)*Lv + j]) / sqrtf(red[0]);
    float o = v * scale;
    __nv_bfloat16 h = __float2bfloat16(o);
    __nv_bfloat16 l = __float2bfloat16(o - __bfloat162float(h));
    size_t d = ((size_t)(b*3 + hm)*Lv + j)*HDv + t;
    if (which) { g_skh[d] = h; g_skl[d] = l; }
    else       { g_sqh[d] = h; g_sql[d] = l; }
}

// ================= symmetric mask -> per-row CSR =================
__global__ void mask_kernel(const int* __restrict__ rns)
{
    int warp = (blockIdx.x * blockDim.x + threadIdx.x) >> 5;
    int lane = threadIdx.x & 31;
    int b = warp >> 11, i = warp & (Tv-1);
    const int* row = rns + (size_t)warp * KIv;
    int j = row[lane];
    bool dup = false;
#pragma unroll
    for (int k2 = 0; k2 < 32; ++k2) {
        int jj = __shfl_sync(0xffffffffu, j, k2);
        if (k2 < lane && jj == j) dup = true;
    }
    bool mem = false;
    const int* rj = rns + (size_t)(b*Tv + j)*KIv;
#pragma unroll
    for (int m = 0; m < 32; ++m) if (rj[m] == i) mem = true;
    bool valid = (!dup) && mem;
    unsigned bal = __ballot_sync(0xffffffffu, valid);
    if (valid) {
        int pos = __popc(bal & ((1u << lane) - 1u));
        g_cols[(size_t)warp*KIv + pos] = j;
    }
    if (lane == 0) g_cnt[warp] = __popc(bal);
}

// ================= column sum of v (zero-nnz rows) =================
__global__ void colsumA()
{
    int g = blockIdx.x*256 + threadIdx.x;
    int chunk = g >> 10;
    int c = g & 1023;
    int b = c >> 9, col = c & 511;
    const float* p = g_v + (size_t)(b*Tv + chunk*256)*NXv + col;
    float s = 0.f;
    for (int t = 0; t < 256; ++t) s += p[(size_t)t*NXv];
    g_vpart[g] = s;
}
__global__ void colsumB()
{
    int c = blockIdx.x*256 + threadIdx.x;
    float s = 0.f;
#pragma unroll
    for (int ch = 0; ch < 8; ++ch) s += g_vpart[ch*1024 + c];
    g_vcolsum[c] = s;
}

// ================= sparse attention rows + wmix + RMSNorm + bf16 split ===========
__global__ void __launch_bounds__(256) attn_rows(const float* __restrict__ rms_g)
{
    const int r = blockIdx.x;
    const int b = r >> 11;
    const int i = r & (Tv-1);
    const int tid = threadIdx.x;
    __shared__ int   scols[KIv];
    __shared__ float sw[3][KIv];
    __shared__ float c0[KIv], c1[KIv];
    __shared__ float red[512];
    const int cnt = g_cnt[r];
    if (tid < KIv && tid < cnt) scols[tid] = g_cols[(size_t)r*KIv + tid];
    __syncthreads();
    const float lam = g_scal[0];
    const int wid = tid >> 5, lane = tid & 31;

    for (int task = wid; task < 3*cnt; task += 8) {
        int hm = task % 3, j = task / 3, h = hm + 1;
        const float* w1p = g_w1  + ((size_t)((b*4+h)*Tv + i)        << 6);
        const float* w2p = g_w2t + ((size_t)((b*4+h)*Tv + scols[j]) << 6);
        float s = w1p[lane]*w2p[lane] + w1p[lane+32]*w2p[lane+32];
#pragma unroll
        for (int o = 16; o; o >>= 1) s += __shfl_xor_sync(0xffffffffu, s, o);
        if (lane == 0) sw[hm][j] = s;
    }
    __syncthreads();

    if (wid == 0 && cnt > 0) {
        float p[3];
#pragma unroll
        for (int hm = 0; hm < 3; ++hm) {
            float x = (lane < cnt) ? sw[hm][lane] : -INFINITY;
            float mx = x;
#pragma unroll
            for (int o = 16; o; o >>= 1) mx = fmaxf(mx, __shfl_xor_sync(0xffffffffu, mx, o));
            float e = (lane < cnt) ? expf(x - mx) : 0.f;
            float sm = e;
#pragma unroll
            for (int o = 16; o; o >>= 1) sm += __shfl_xor_sync(0xffffffffu, sm, o);
            p[hm] = e / sm;
        }
        if (lane < cnt) {
            c0[lane] = (1.f - lam)*p[1] - lam*p[0];
            c1[lane] = p[1] - p[0] + (1.f - 2.f*lam)*p[2];
        }
    }
    __syncthreads();

    float s0 = 0.f, s1 = 0.f;
    if (cnt > 0) {
#pragma unroll 4
        for (int j = 0; j < cnt; ++j) {
            const float* vp = g_v + ((size_t)(b*Tv + scols[j]) << 9);
            s0 += c0[j] * vp[tid];
            s1 += c1[j] * vp[tid + 256];
        }
    } else {
        float u = (1.f - 2.f*lam) * (1.f/(float)Tv);
        s0 = u * g_vcolsum[b*NXv + tid];
        s1 = u * g_vcolsum[b*NXv + tid + 256];
    }

    red[tid]       = s0*s0;
    red[tid + 256] = s1*s1;
    __syncthreads();
#pragma unroll
    for (int o = 128; o; o >>= 1) {
        if (tid < o) { red[tid] += red[tid+o]; red[256+tid] += red[256+tid+o]; }
        __syncthreads();
    }
    float onem = g_scal[1];
    float g = rms_g[tid];
    float a0 = s0 * rsqrtf(red[0]  *(1.f/256.f) + 1e-5f) * g * onem;
    float a1 = s1 * rsqrtf(red[256]*(1.f/256.f) + 1e-5f) * g * onem;
    __nv_bfloat16 h0 = __float2bfloat16(a0);
    __nv_bfloat16 h1 = __float2bfloat16(a1);
    size_t o0 = (size_t)r*NXv + tid, o1 = o0 + 256;
    g_ah[o0] = h0;                                   g_ah[o1] = h1;
    g_al[o0] = __float2bfloat16(a0 - __bfloat162float(h0));
    g_al[o1] = __float2bfloat16(a1 - __bfloat162float(h1));
}

// ================= launch =================
extern "C" void kernel_launch(void* const* d_in, const int* in_sizes, int n_in,
                              void* d_out, int out_size)
{
    const float* x    = (const float*)d_in[0];
    const float* wq   = (const float*)d_in[1];
    const float* wk   = (const float*)d_in[2];
    const float* wv   = (const float*)d_in[3];
    const float* wo   = (const float*)d_in[4];
    const float* m1   = (const float*)d_in[5];
    const float* m2   = (const float*)d_in[6];
    const float* lq1  = (const float*)d_in[7];
    const float* lk1  = (const float*)d_in[8];
    const float* lq2  = (const float*)d_in[9];
    const float* lk2  = (const float*)d_in[10];
    const float* rmsg = (const float*)d_in[11];
    const int*   lp   = (const int*)d_in[12];
    const int*   rns  = (const int*)d_in[14];
    const int*   lmk  = (const int*)d_in[15];
    float* out = (float*)d_out;

    cudaFuncSetAttribute(gemm_qkv,   cudaFuncAttributeMaxDynamicSharedMemorySize, GEMM_SMEM_TOTAL);
    cudaFuncSetAttribute(gemm_out,   cudaFuncAttributeMaxDynamicSharedMemorySize, GEMM_SMEM_TOTAL);
    cudaFuncSetAttribute(gemm_w_mma, cudaFuncAttributeMaxDynamicSharedMemorySize, GW_SMEM);

    lam_kernel<<<1, 128>>>(lq1, lk1, lq2, lk2, lp);
    split_x<<<(Bv*Tv*NXv)/512, 256>>>((const float2*)x);
    split_w<<<dim3(NN/512, 4), 256>>>((const float2*)wq, (const float2*)wk,
                                      (const float2*)wv, (const float2*)wo);

    gemm_qkv<<<dim3(Bv*Tv/128, 10), 512, GEMM_SMEM_TOTAL>>>();

    sqsk_kernel<<<2*Bv*3*Lv, 128>>>(lmk, m1, m2);
    gemm_w_mma<<<dim3(Tv/128, Bv*3, 2), 256, GW_SMEM>>>();

    mask_kernel<<<Bv*Tv*32/256, 256>>>(rns);
    colsumA<<<32, 256>>>();
    colsumB<<<4, 256>>>();
    attn_rows<<<Bv*Tv, 256>>>(rmsg);

    gemm_out<<<dim3(Bv*Tv/128, 4), 512, GEMM_SMEM_TOTAL>>>(out);
}

// round 6
// speedup vs baseline: 2.8307x; 1.1100x over previous
#include <cuda_runtime.h>
#include <cuda_bf16.h>
#include <math.h>
#include <cstdint>

#define Bv 2
#define Tv 2048
#define NXv 512
#define HDv 128
#define Lv 64
#define KIv 32
#define NN (NXv*NXv)
#define QKW 384   // pruned q/k width (heads 1..3)

// ================= scratch (device globals; no allocation allowed) =================
__device__ float g_v[Bv*Tv*NXv];
__device__ float g_w1 [Bv*4*Tv*Lv];
__device__ float g_w2t[Bv*4*Tv*Lv];
__device__ int   g_cols[Bv*Tv*KIv];
__device__ int   g_cnt [Bv*Tv];
__device__ float g_vpart[8*Bv*NXv];
__device__ float g_vcolsum[Bv*NXv];
__device__ float g_scal[2];
__device__ __nv_bfloat16 g_xh[Bv*Tv*NXv], g_xl[Bv*Tv*NXv];
__device__ __nv_bfloat16 g_ah[Bv*Tv*NXv], g_al[Bv*Tv*NXv];
__device__ __nv_bfloat16 g_wh[4*NN], g_wl[4*NN];
__device__ __nv_bfloat16 g_qh[Bv*Tv*QKW], g_ql[Bv*Tv*QKW];
__device__ __nv_bfloat16 g_kh[Bv*Tv*QKW], g_kl[Bv*Tv*QKW];
__device__ __nv_bfloat16 g_skh[Bv*3*Lv*HDv], g_skl[Bv*3*Lv*HDv];
__device__ __nv_bfloat16 g_sqh[Bv*3*Lv*HDv], g_sql[Bv*3*Lv*HDv];

// ================= helpers =================
__device__ __forceinline__ uint32_t smem_u32(const void* p) {
    uint32_t a;
    asm("{ .reg .u64 t; cvta.to.shared.u64 t, %1; cvt.u32.u64 %0, t; }" : "=r"(a) : "l"(p));
    return a;
}
__device__ __forceinline__ uint32_t sw128(uint32_t off) { return off ^ ((off >> 3) & 0x70); }

#define CP16(dst, src)  asm volatile("cp.async.cg.shared.global [%0], [%1], 16;" :: "r"(dst), "l"(src) : "memory")
#define CP_COMMIT()     asm volatile("cp.async.commit_group;" ::: "memory")

#define LDSM4(r, a) \
    asm volatile("ldmatrix.sync.aligned.m8n8.x4.shared.b16 {%0,%1,%2,%3}, [%4];" \
        : "=r"((r)[0]), "=r"((r)[1]), "=r"((r)[2]), "=r"((r)[3]) : "r"(a))

#define MMA16816(d, a, b) \
    asm volatile("mma.sync.aligned.m16n8k16.row.col.f32.bf16.bf16.f32 " \
        "{%0,%1,%2,%3},{%4,%5,%6,%7},{%8,%9},{%0,%1,%2,%3};" \
        : "+f"((d)[0]), "+f"((d)[1]), "+f"((d)[2]), "+f"((d)[3]) \
        : "r"((a)[0]), "r"((a)[1]), "r"((a)[2]), "r"((a)[3]), "r"((b)[0]), "r"((b)[1]))

// ================= 256-thread split-bf16 MMA mainloop: 64x128 tile, K=512 ==========
// Warp grid 2(M)x4(N), warp tile 32x32. Stage = Ah(8K)+Al(8K)+Bh(16K)+Bl(16K)=48KB,
// 2 stages = 96KB -> 2 CTAs/SM (regs and smem both fit).
#define STAGE_BYTES 49152
#define GEMM_SMEM_TOTAL (2*STAGE_BYTES)

__device__ __forceinline__ void mainloop64(
    const __nv_bfloat16* __restrict__ Ah, const __nv_bfloat16* __restrict__ Al,
    const __nv_bfloat16* __restrict__ Bh, const __nv_bfloat16* __restrict__ Bl,
    int m0, char* smem, float acc[2][4][4])
{
    const uint32_t sb = smem_u32(smem);
    const int tid = threadIdx.x, lane = tid & 31;
    const int wid = tid >> 5;
    const int wm = wid & 1, wn = wid >> 1;

    auto load_stage = [&](int kc, uint32_t dstb) {
        // A tiles: 64 rows x 64 K (128B/row), hi + lo
#pragma unroll
        for (int t = 0; t < 2; ++t) {
            const __nv_bfloat16* base = t ? Al : Ah;
#pragma unroll
            for (int j = 0; j < 2; ++j) {
                int idx = j * 256 + tid;            // 0..511
                int row = idx >> 3, c = idx & 7;
                CP16(dstb + t * 8192 + sw128((uint32_t)(row * 128 + c * 16)),
                     base + (size_t)(m0 + row) * 512 + kc * 64 + c * 8);
            }
        }
        // B tiles: 128 rows x 64 K, hi + lo
#pragma unroll
        for (int t = 0; t < 2; ++t) {
            const __nv_bfloat16* base = t ? Bl : Bh;
#pragma unroll
            for (int j = 0; j < 4; ++j) {
                int idx = j * 256 + tid;            // 0..1023
                int row = idx >> 3, c = idx & 7;
                CP16(dstb + 16384 + t * 16384 + sw128((uint32_t)(row * 128 + c * 16)),
                     base + (size_t)row * 512 + kc * 64 + c * 8);
            }
        }
    };

    load_stage(0, sb);
    CP_COMMIT();

    for (int kc = 0; kc < 8; ++kc) {
        if (kc < 7) {
            load_stage(kc + 1, sb + ((kc + 1) & 1) * STAGE_BYTES);
            CP_COMMIT();
            asm volatile("cp.async.wait_group 1;" ::: "memory");
        } else {
            asm volatile("cp.async.wait_group 0;" ::: "memory");
        }
        __syncthreads();
        const uint32_t sbuf = sb + (kc & 1) * STAGE_BYTES;

#pragma unroll
        for (int kk = 0; kk < 4; ++kk) {
            const int klo = kk * 2;
            uint32_t ah[2][4], al[2][4], bh[4][2], bl[4][2];
            const int arow = ((lane >> 3) & 1) * 8 + (lane & 7);
            const int achk = klo + (lane >> 4);
#pragma unroll
            for (int f = 0; f < 2; ++f) {
                uint32_t off = sw128((uint32_t)((wm * 32 + f * 16 + arow) * 128 + achk * 16));
                LDSM4(ah[f], sbuf + off);
                LDSM4(al[f], sbuf + 8192 + off);
            }
            const int brow = (lane >> 4) * 8 + (lane & 7);
            const int bchk = klo + ((lane >> 3) & 1);
#pragma unroll
            for (int p = 0; p < 2; ++p) {
                uint32_t off = sw128((uint32_t)((wn * 32 + p * 16 + brow) * 128 + bchk * 16));
                uint32_t r[4];
                LDSM4(r, sbuf + 16384 + off);
                bh[2*p][0] = r[0]; bh[2*p][1] = r[1];
                bh[2*p+1][0] = r[2]; bh[2*p+1][1] = r[3];
                LDSM4(r, sbuf + 32768 + off);
                bl[2*p][0] = r[0]; bl[2*p][1] = r[1];
                bl[2*p+1][0] = r[2]; bl[2*p+1][1] = r[3];
            }
#pragma unroll
            for (int f = 0; f < 2; ++f)
#pragma unroll
                for (int n = 0; n < 4; ++n) {
                    MMA16816(acc[f][n], ah[f], bh[n]);
                    MMA16816(acc[f][n], ah[f], bl[n]);
                    MMA16816(acc[f][n], al[f], bh[n]);
                }
        }
        __syncthreads();
    }
}

// Fused q/k/v projection. grid (64, 10):
//  y 0..2 : q cols 128..511 -> bf16 (hi,lo) pruned [4096, 384]
//  y 3..5 : k cols 128..511 -> bf16 (hi,lo) pruned
//  y 6..9 : v cols 0..511   -> fp32
__global__ void __launch_bounds__(256, 2) gemm_qkv()
{
    extern __shared__ char smem[];
    const int y = blockIdx.y;
    int widx, brow;
    if (y < 3)      { widx = 0; brow = 128 + y * 128; }
    else if (y < 6) { widx = 1; brow = 128 + (y - 3) * 128; }
    else            { widx = 2; brow = (y - 6) * 128; }
    const int m0 = blockIdx.x * 64;

    float acc[2][4][4] = {};
    mainloop64(g_xh, g_xl,
               g_wh + (size_t)widx * NN + (size_t)brow * 512,
               g_wl + (size_t)widx * NN + (size_t)brow * 512,
               m0, smem, acc);

    const int tid = threadIdx.x, lane = tid & 31;
    const int wid = tid >> 5;
    const int wm = wid & 1, wn = wid >> 1;
    const int r0 = m0 + wm * 32 + (lane >> 2);
    const int c0 = wn * 32 + (lane & 3) * 2;

    if (y < 6) {
        __nv_bfloat16* dh = widx ? g_kh : g_qh;
        __nv_bfloat16* dl = widx ? g_kl : g_ql;
        const int cp0 = (brow - 128) + c0;
#pragma unroll
        for (int f = 0; f < 2; ++f)
#pragma unroll
            for (int n = 0; n < 4; ++n) {
#pragma unroll
                for (int hr = 0; hr < 2; ++hr) {
                    const int row = r0 + f * 16 + hr * 8;
                    float v0 = acc[f][n][hr*2], v1 = acc[f][n][hr*2+1];
                    __nv_bfloat16 h0 = __float2bfloat16(v0), h1 = __float2bfloat16(v1);
                    size_t o = (size_t)row * QKW + cp0 + n * 8;
                    *(__nv_bfloat162*)(dh + o) = __halves2bfloat162(h0, h1);
                    *(__nv_bfloat162*)(dl + o) = __halves2bfloat162(
                        __float2bfloat16(v0 - __bfloat162float(h0)),
                        __float2bfloat16(v1 - __bfloat162float(h1)));
                }
            }
    } else {
#pragma unroll
        for (int f = 0; f < 2; ++f)
#pragma unroll
            for (int n = 0; n < 4; ++n) {
                float* p0 = g_v + (size_t)(r0 + f * 16) * 512 + brow + c0 + n * 8;
                *(float2*)p0 = make_float2(acc[f][n][0], acc[f][n][1]);
                *(float2*)(p0 + 8 * 512) = make_float2(acc[f][n][2], acc[f][n][3]);
            }
    }
}

// Output projection: out = a @ wo^T. grid (64, 4).
__global__ void __launch_bounds__(256, 2) gemm_out(float* __restrict__ out)
{
    extern __shared__ char smem[];
    const int brow = blockIdx.y * 128;
    const int m0 = blockIdx.x * 64;
    float acc[2][4][4] = {};
    mainloop64(g_ah, g_al,
               g_wh + 3ull * NN + (size_t)brow * 512,
               g_wl + 3ull * NN + (size_t)brow * 512,
               m0, smem, acc);
    const int tid = threadIdx.x, lane = tid & 31;
    const int wid = tid >> 5;
    const int wm = wid & 1, wn = wid >> 1;
    const int r0 = m0 + wm * 32 + (lane >> 2);
    const int c0 = brow + wn * 32 + (lane & 3) * 2;
#pragma unroll
    for (int f = 0; f < 2; ++f)
#pragma unroll
        for (int n = 0; n < 4; ++n) {
            float* p0 = out + (size_t)(r0 + f * 16) * 512 + c0 + n * 8;
            *(float2*)p0 = make_float2(acc[f][n][0], acc[f][n][1]);
            *(float2*)(p0 + 8 * 512) = make_float2(acc[f][n][2], acc[f][n][3]);
        }
}

// ================= gemm_w via MMA: w1 = q.sk^T, w2t = k.sq^T ======================
// C[128,64] per CTA; A [4096, 384] bf16 pruned, K=128 (head dim); B [64, 128].
// grid (16, 6, 2): x = t-tile, y = b*3+hm, z = second. 256 threads, warp grid 4x2.
#define GW_SMEM (2*49152)
__global__ void __launch_bounds__(256, 2) gemm_w_mma()
{
    extern __shared__ char smem[];
    const uint32_t sb = smem_u32(smem);
    const int tid = threadIdx.x, lane = tid & 31;
    const int wm = (tid >> 5) & 3, wn = tid >> 7;
    const int second = blockIdx.z;
    const int bh_ = blockIdx.y;
    const int b = bh_ / 3, hm = bh_ % 3;
    const int m0 = blockIdx.x * 128;

    const __nv_bfloat16* Ah = (second ? g_kh : g_qh) + (size_t)b*Tv*QKW + hm*HDv;
    const __nv_bfloat16* Al = (second ? g_kl : g_ql) + (size_t)b*Tv*QKW + hm*HDv;
    const __nv_bfloat16* Bh = (second ? g_sqh : g_skh) + (size_t)bh_*Lv*HDv;
    const __nv_bfloat16* Bl = (second ? g_sql : g_skl) + (size_t)bh_*Lv*HDv;
    float* C = (second ? g_w2t : g_w1) + ((size_t)((b*4+hm+1)*Tv) + m0) * Lv;

    float acc[2][4][4] = {};

    auto load_stage = [&](int kc, uint32_t dstb) {
#pragma unroll
        for (int t = 0; t < 2; ++t) {
            const __nv_bfloat16* base = t ? Al : Ah;
#pragma unroll
            for (int j = 0; j < 4; ++j) {
                int idx = j * 256 + tid;
                int row = idx >> 3, c = idx & 7;
                const void* src = base + (size_t)(m0 + row) * QKW + kc * 64 + c * 8;
                uint32_t dst = dstb + t * 16384 + sw128((uint32_t)(row * 128 + c * 16));
                CP16(dst, src);
            }
        }
#pragma unroll
        for (int t = 0; t < 2; ++t) {
            const __nv_bfloat16* base = t ? Bl : Bh;
#pragma unroll
            for (int j = 0; j < 2; ++j) {
                int idx = j * 256 + tid;
                int row = idx >> 3, c = idx & 7;
                const void* src = base + (size_t)row * HDv + kc * 64 + c * 8;
                uint32_t dst = dstb + 32768 + t * 8192 + sw128((uint32_t)(row * 128 + c * 16));
                CP16(dst, src);
            }
        }
    };

    load_stage(0, sb); CP_COMMIT();
    load_stage(1, sb + 49152); CP_COMMIT();

    for (int kc = 0; kc < 2; ++kc) {
        if (kc == 0) asm volatile("cp.async.wait_group 1;" ::: "memory");
        else         asm volatile("cp.async.wait_group 0;" ::: "memory");
        __syncthreads();
        const uint32_t sbuf = sb + kc * 49152;
#pragma unroll
        for (int kk = 0; kk < 4; ++kk) {
            const int klo = kk * 2;
            uint32_t ah[2][4], al[2][4], bh[4][2], bl[4][2];
            const int arow = ((lane >> 3) & 1) * 8 + (lane & 7);
            const int achk = klo + (lane >> 4);
#pragma unroll
            for (int f = 0; f < 2; ++f) {
                uint32_t off = sw128((uint32_t)((wm * 32 + f * 16 + arow) * 128 + achk * 16));
                LDSM4(ah[f], sbuf + off);
                LDSM4(al[f], sbuf + 16384 + off);
            }
            const int brow = (lane >> 4) * 8 + (lane & 7);
            const int bchk = klo + ((lane >> 3) & 1);
#pragma unroll
            for (int p = 0; p < 2; ++p) {
                uint32_t off = sw128((uint32_t)((wn * 32 + p * 16 + brow) * 128 + bchk * 16));
                uint32_t r[4];
                LDSM4(r, sbuf + 32768 + off);
                bh[2*p][0] = r[0]; bh[2*p][1] = r[1];
                bh[2*p+1][0] = r[2]; bh[2*p+1][1] = r[3];
                LDSM4(r, sbuf + 40960 + off);
                bl[2*p][0] = r[0]; bl[2*p][1] = r[1];
                bl[2*p+1][0] = r[2]; bl[2*p+1][1] = r[3];
            }
#pragma unroll
            for (int f = 0; f < 2; ++f)
#pragma unroll
                for (int n = 0; n < 4; ++n) {
                    MMA16816(acc[f][n], ah[f], bh[n]);
                    MMA16816(acc[f][n], ah[f], bl[n]);
                    MMA16816(acc[f][n], al[f], bh[n]);
                }
        }
        __syncthreads();
    }

    const int r0 = wm * 32 + (lane >> 2);
    const int c0 = wn * 32 + (lane & 3) * 2;
#pragma unroll
    for (int f = 0; f < 2; ++f)
#pragma unroll
        for (int n = 0; n < 4; ++n) {
            float* p0 = C + (size_t)(r0 + f * 16) * Lv + c0 + n * 8;
            *(float2*)p0 = make_float2(acc[f][n][0], acc[f][n][1]);
            *(float2*)(p0 + 8 * Lv) = make_float2(acc[f][n][2], acc[f][n][3]);
        }
}

// ================= fused fp32 -> (hi,lo) bf16 split (x + 4 weights) =================
// grid 6144: blocks [0,4096) -> x, [4096,6144) -> weights (512 blocks each)
__global__ void split_all(const float2* __restrict__ x,
                          const float2* __restrict__ w0, const float2* __restrict__ w1,
                          const float2* __restrict__ w2, const float2* __restrict__ w3)
{
    int bid = blockIdx.x;
    const float2* src;
    __nv_bfloat162 *dh, *dl;
    size_t i;
    if (bid < 4096) {
        i = (size_t)bid * 256 + threadIdx.x;
        src = x; dh = (__nv_bfloat162*)g_xh; dl = (__nv_bfloat162*)g_xl;
    } else {
        int r = bid - 4096;
        int widx = r >> 9;
        i = (size_t)(r & 511) * 256 + threadIdx.x;
        src = (widx == 0) ? w0 : (widx == 1) ? w1 : (widx == 2) ? w2 : w3;
        dh = (__nv_bfloat162*)g_wh + (size_t)widx * (NN/2);
        dl = (__nv_bfloat162*)g_wl + (size_t)widx * (NN/2);
    }
    float2 v = src[i];
    __nv_bfloat16 h0 = __float2bfloat16(v.x);
    __nv_bfloat16 h1 = __float2bfloat16(v.y);
    dh[i] = __halves2bfloat162(h0, h1);
    dl[i] = __halves2bfloat162(__float2bfloat16(v.x - __bfloat162float(h0)),
                               __float2bfloat16(v.y - __bfloat162float(h1)));
}

// ================= lam scalar =================
__global__ void lam_kernel(const float* __restrict__ lq1, const float* __restrict__ lk1,
                           const float* __restrict__ lq2, const float* __restrict__ lk2,
                           const int* __restrict__ lptr)
{
    __shared__ float r1[128], r2[128];
    int t = threadIdx.x;
    r1[t] = lq1[t]*lk1[t];
    r2[t] = lq2[t]*lk2[t];
    __syncthreads();
    for (int o = 64; o; o >>= 1) {
        if (t < o) { r1[t] += r1[t+o]; r2[t] += r2[t+o]; }
        __syncthreads();
    }
    if (t == 0) {
        float lam_init = 0.8f - 0.6f*expf(-0.3f*(float)lptr[0]);
        g_scal[0] = expf(r1[0]) - expf(r2[0]) + lam_init;
        g_scal[1] = 1.0f - lam_init;
    }
}

// ================= sq / sk: reconstruct, normalize, scale, re-split ==============
__global__ void sqsk_kernel(const int* __restrict__ landmark,
                            const float* __restrict__ m1,
                            const float* __restrict__ m2)
{
    int idx = blockIdx.x;
    int which = idx & 1;            // 0: sq (from q, m1)  1: sk (from k, m2)
    int rest = idx >> 1;
    int j  = rest % Lv;
    int hm = (rest / Lv) % 3;
    int b  = rest / (Lv*3);
    int t  = threadIdx.x;           // 0..127
    int tok = landmark[j];
    size_t off = (size_t)(b*Tv + tok)*QKW + hm*HDv + t;
    float v = which
        ? (__bfloat162float(g_kh[off]) + __bfloat162float(g_kl[off]))
        : (__bfloat162float(g_qh[off]) + __bfloat162float(g_ql[off]));
    __shared__ float red[128];
    red[t] = v*v;
    __syncthreads();
    for (int o = 64; o; o >>= 1) { if (t < o) red[t] += red[t+o]; __syncthreads(); }
    float scale = (which ? m2[(hm+1)*Lv + j] : m1[(hm+1)*Lv + j]) / sqrtf(red[0]);
    float o = v * scale;
    __nv_bfloat16 h = __float2bfloat16(o);
    __nv_bfloat16 l = __float2bfloat16(o - __bfloat162float(h));
    size_t d = ((size_t)(b*3 + hm)*Lv + j)*HDv + t;
    if (which) { g_skh[d] = h; g_skl[d] = l; }
    else       { g_sqh[d] = h; g_sql[d] = l; }
}

// ================= symmetric mask -> per-row CSR =================
__global__ void mask_kernel(const int* __restrict__ rns)
{
    int warp = (blockIdx.x * blockDim.x + threadIdx.x) >> 5;
    int lane = threadIdx.x & 31;
    int b = warp >> 11, i = warp & (Tv-1);
    const int* row = rns + (size_t)warp * KIv;
    int j = row[lane];
    bool dup = false;
#pragma unroll
    for (int k2 = 0; k2 < 32; ++k2) {
        int jj = __shfl_sync(0xffffffffu, j, k2);
        if (k2 < lane && jj == j) dup = true;
    }
    bool mem = false;
    const int* rj = rns + (size_t)(b*Tv + j)*KIv;
#pragma unroll
    for (int m = 0; m < 32; ++m) if (rj[m] == i) mem = true;
    bool valid = (!dup) && mem;
    unsigned bal = __ballot_sync(0xffffffffu, valid);
    if (valid) {
        int pos = __popc(bal & ((1u << lane) - 1u));
        g_cols[(size_t)warp*KIv + pos] = j;
    }
    if (lane == 0) g_cnt[warp] = __popc(bal);
}

// ================= column sum of v (zero-nnz rows) =================
__global__ void colsumA()
{
    int g = blockIdx.x*256 + threadIdx.x;
    int chunk = g >> 10;
    int c = g & 1023;
    int b = c >> 9, col = c & 511;
    const float* p = g_v + (size_t)(b*Tv + chunk*256)*NXv + col;
    float s = 0.f;
    for (int t = 0; t < 256; ++t) s += p[(size_t)t*NXv];
    g_vpart[g] = s;
}
__global__ void colsumB()
{
    int c = blockIdx.x*256 + threadIdx.x;
    float s = 0.f;
#pragma unroll
    for (int ch = 0; ch < 8; ++ch) s += g_vpart[ch*1024 + c];
    g_vcolsum[c] = s;
}

// ================= sparse attention rows + wmix + RMSNorm + bf16 split ===========
__global__ void __launch_bounds__(256) attn_rows(const float* __restrict__ rms_g)
{
    const int r = blockIdx.x;
    const int b = r >> 11;
    const int i = r & (Tv-1);
    const int tid = threadIdx.x;
    __shared__ int   scols[KIv];
    __shared__ float sw[3][KIv];
    __shared__ float c0[KIv], c1[KIv];
    __shared__ float red[512];
    const int cnt = g_cnt[r];
    if (tid < KIv && tid < cnt) scols[tid] = g_cols[(size_t)r*KIv + tid];
    __syncthreads();
    const float lam = g_scal[0];
    const int wid = tid >> 5, lane = tid & 31;

    for (int task = wid; task < 3*cnt; task += 8) {
        int hm = task % 3, j = task / 3, h = hm + 1;
        const float* w1p = g_w1  + ((size_t)((b*4+h)*Tv + i)        << 6);
        const float* w2p = g_w2t + ((size_t)((b*4+h)*Tv + scols[j]) << 6);
        float s = w1p[lane]*w2p[lane] + w1p[lane+32]*w2p[lane+32];
#pragma unroll
        for (int o = 16; o; o >>= 1) s += __shfl_xor_sync(0xffffffffu, s, o);
        if (lane == 0) sw[hm][j] = s;
    }
    __syncthreads();

    if (wid == 0 && cnt > 0) {
        float p[3];
#pragma unroll
        for (int hm = 0; hm < 3; ++hm) {
            float x = (lane < cnt) ? sw[hm][lane] : -INFINITY;
            float mx = x;
#pragma unroll
            for (int o = 16; o; o >>= 1) mx = fmaxf(mx, __shfl_xor_sync(0xffffffffu, mx, o));
            float e = (lane < cnt) ? expf(x - mx) : 0.f;
            float sm = e;
#pragma unroll
            for (int o = 16; o; o >>= 1) sm += __shfl_xor_sync(0xffffffffu, sm, o);
            p[hm] = e / sm;
        }
        if (lane < cnt) {
            c0[lane] = (1.f - lam)*p[1] - lam*p[0];
            c1[lane] = p[1] - p[0] + (1.f - 2.f*lam)*p[2];
        }
    }
    __syncthreads();

    float s0 = 0.f, s1 = 0.f;
    if (cnt > 0) {
#pragma unroll 4
        for (int j = 0; j < cnt; ++j) {
            const float* vp = g_v + ((size_t)(b*Tv + scols[j]) << 9);
            s0 += c0[j] * vp[tid];
            s1 += c1[j] * vp[tid + 256];
        }
    } else {
        float u = (1.f - 2.f*lam) * (1.f/(float)Tv);
        s0 = u * g_vcolsum[b*NXv + tid];
        s1 = u * g_vcolsum[b*NXv + tid + 256];
    }

    red[tid]       = s0*s0;
    red[tid + 256] = s1*s1;
    __syncthreads();
#pragma unroll
    for (int o = 128; o; o >>= 1) {
        if (tid < o) { red[tid] += red[tid+o]; red[256+tid] += red[256+tid+o]; }
        __syncthreads();
    }
    float onem = g_scal[1];
    float g = rms_g[tid];
    float a0 = s0 * rsqrtf(red[0]  *(1.f/256.f) + 1e-5f) * g * onem;
    float a1 = s1 * rsqrtf(red[256]*(1.f/256.f) + 1e-5f) * g * onem;
    __nv_bfloat16 h0 = __float2bfloat16(a0);
    __nv_bfloat16 h1 = __float2bfloat16(a1);
    size_t o0 = (size_t)r*NXv + tid, o1 = o0 + 256;
    g_ah[o0] = h0;                                   g_ah[o1] = h1;
    g_al[o0] = __float2bfloat16(a0 - __bfloat162float(h0));
    g_al[o1] = __float2bfloat16(a1 - __bfloat162float(h1));
}

// ================= launch =================
extern "C" void kernel_launch(void* const* d_in, const int* in_sizes, int n_in,
                              void* d_out, int out_size)
{
    const float* x    = (const float*)d_in[0];
    const float* wq   = (const float*)d_in[1];
    const float* wk   = (const float*)d_in[2];
    const float* wv   = (const float*)d_in[3];
    const float* wo   = (const float*)d_in[4];
    const float* m1   = (const float*)d_in[5];
    const float* m2   = (const float*)d_in[6];
    const float* lq1  = (const float*)d_in[7];
    const float* lk1  = (const float*)d_in[8];
    const float* lq2  = (const float*)d_in[9];
    const float* lk2  = (const float*)d_in[10];
    const float* rmsg = (const float*)d_in[11];
    const int*   lp   = (const int*)d_in[12];
    const int*   rns  = (const int*)d_in[14];
    const int*   lmk  = (const int*)d_in[15];
    float* out = (float*)d_out;

    cudaFuncSetAttribute(gemm_qkv,   cudaFuncAttributeMaxDynamicSharedMemorySize, GEMM_SMEM_TOTAL);
    cudaFuncSetAttribute(gemm_out,   cudaFuncAttributeMaxDynamicSharedMemorySize, GEMM_SMEM_TOTAL);
    cudaFuncSetAttribute(gemm_w_mma, cudaFuncAttributeMaxDynamicSharedMemorySize, GW_SMEM);

    lam_kernel<<<1, 128>>>(lq1, lk1, lq2, lk2, lp);
    split_all<<<6144, 256>>>((const float2*)x, (const float2*)wq, (const float2*)wk,
                             (const float2*)wv, (const float2*)wo);

    gemm_qkv<<<dim3(Bv*Tv/64, 10), 256, GEMM_SMEM_TOTAL>>>();

    sqsk_kernel<<<2*Bv*3*Lv, 128>>>(lmk, m1, m2);
    gemm_w_mma<<<dim3(Tv/128, Bv*3, 2), 256, GW_SMEM>>>();

    mask_kernel<<<Bv*Tv*32/256, 256>>>(rns);
    colsumA<<<32, 256>>>();
    colsumB<<<4, 256>>>();
    attn_rows<<<Bv*Tv, 256>>>(rmsg);

    gemm_out<<<dim3(Bv*Tv/64, 4), 256, GEMM_SMEM_TOTAL>>>(out);
}

// round 7
// speedup vs baseline: 3.0912x; 1.0920x over previous
#include <cuda_runtime.h>
#include <cuda_bf16.h>
#include <math.h>
#include <cstdint>

#define Bv 2
#define Tv 2048
#define NXv 512
#define HDv 128
#define Lv 64
#define KIv 32
#define NN (NXv*NXv)
#define QKW 384   // pruned q/k width (heads 1..3)

// ================= scratch (device globals; no allocation allowed) =================
__device__ float g_v[Bv*Tv*NXv];
__device__ float g_w1 [Bv*4*Tv*Lv];
__device__ float g_w2t[Bv*4*Tv*Lv];
__device__ int   g_cols[Bv*Tv*KIv];
__device__ int   g_cnt [Bv*Tv];
__device__ float g_vpart[8*Bv*NXv];
__device__ float g_scal[2];
__device__ __nv_bfloat16 g_xh[Bv*Tv*NXv], g_xl[Bv*Tv*NXv];
__device__ __nv_bfloat16 g_ah[Bv*Tv*NXv], g_al[Bv*Tv*NXv];
__device__ __nv_bfloat16 g_wh[4*NN], g_wl[4*NN];
__device__ __nv_bfloat16 g_qh[Bv*Tv*QKW], g_ql[Bv*Tv*QKW];
__device__ __nv_bfloat16 g_kh[Bv*Tv*QKW], g_kl[Bv*Tv*QKW];
__device__ __nv_bfloat16 g_skh[Bv*3*Lv*HDv], g_skl[Bv*3*Lv*HDv];
__device__ __nv_bfloat16 g_sqh[Bv*3*Lv*HDv], g_sql[Bv*3*Lv*HDv];

// ================= helpers =================
__device__ __forceinline__ uint32_t smem_u32(const void* p) {
    uint32_t a;
    asm("{ .reg .u64 t; cvta.to.shared.u64 t, %1; cvt.u32.u64 %0, t; }" : "=r"(a) : "l"(p));
    return a;
}
__device__ __forceinline__ uint32_t sw128(uint32_t off) { return off ^ ((off >> 3) & 0x70); }

#define CP16(dst, src)  asm volatile("cp.async.cg.shared.global [%0], [%1], 16;" :: "r"(dst), "l"(src) : "memory")
#define CP_COMMIT()     asm volatile("cp.async.commit_group;" ::: "memory")

#define LDSM4(r, a) \
    asm volatile("ldmatrix.sync.aligned.m8n8.x4.shared.b16 {%0,%1,%2,%3}, [%4];" \
        : "=r"((r)[0]), "=r"((r)[1]), "=r"((r)[2]), "=r"((r)[3]) : "r"(a))

#define MMA16816(d, a, b) \
    asm volatile("mma.sync.aligned.m16n8k16.row.col.f32.bf16.bf16.f32 " \
        "{%0,%1,%2,%3},{%4,%5,%6,%7},{%8,%9},{%0,%1,%2,%3};" \
        : "+f"((d)[0]), "+f"((d)[1]), "+f"((d)[2]), "+f"((d)[3]) \
        : "r"((a)[0]), "r"((a)[1]), "r"((a)[2]), "r"((a)[3]), "r"((b)[0]), "r"((b)[1]))

// ================= 256-thread split-bf16 MMA mainloop: 64x128 tile, K=512 ==========
#define STAGE_BYTES 49152
#define GEMM_SMEM_TOTAL (2*STAGE_BYTES)

__device__ __forceinline__ void mainloop64(
    const __nv_bfloat16* __restrict__ Ah, const __nv_bfloat16* __restrict__ Al,
    const __nv_bfloat16* __restrict__ Bh, const __nv_bfloat16* __restrict__ Bl,
    int m0, char* smem, float acc[2][4][4])
{
    const uint32_t sb = smem_u32(smem);
    const int tid = threadIdx.x, lane = tid & 31;
    const int wid = tid >> 5;
    const int wm = wid & 1, wn = wid >> 1;

    auto load_stage = [&](int kc, uint32_t dstb) {
#pragma unroll
        for (int t = 0; t < 2; ++t) {
            const __nv_bfloat16* base = t ? Al : Ah;
#pragma unroll
            for (int j = 0; j < 2; ++j) {
                int idx = j * 256 + tid;
                int row = idx >> 3, c = idx & 7;
                CP16(dstb + t * 8192 + sw128((uint32_t)(row * 128 + c * 16)),
                     base + (size_t)(m0 + row) * 512 + kc * 64 + c * 8);
            }
        }
#pragma unroll
        for (int t = 0; t < 2; ++t) {
            const __nv_bfloat16* base = t ? Bl : Bh;
#pragma unroll
            for (int j = 0; j < 4; ++j) {
                int idx = j * 256 + tid;
                int row = idx >> 3, c = idx & 7;
                CP16(dstb + 16384 + t * 16384 + sw128((uint32_t)(row * 128 + c * 16)),
                     base + (size_t)row * 512 + kc * 64 + c * 8);
            }
        }
    };

    load_stage(0, sb);
    CP_COMMIT();

    for (int kc = 0; kc < 8; ++kc) {
        if (kc < 7) {
            load_stage(kc + 1, sb + ((kc + 1) & 1) * STAGE_BYTES);
            CP_COMMIT();
            asm volatile("cp.async.wait_group 1;" ::: "memory");
        } else {
            asm volatile("cp.async.wait_group 0;" ::: "memory");
        }
        __syncthreads();
        const uint32_t sbuf = sb + (kc & 1) * STAGE_BYTES;

#pragma unroll
        for (int kk = 0; kk < 4; ++kk) {
            const int klo = kk * 2;
            uint32_t ah[2][4], al[2][4], bh[4][2], bl[4][2];
            const int arow = ((lane >> 3) & 1) * 8 + (lane & 7);
            const int achk = klo + (lane >> 4);
#pragma unroll
            for (int f = 0; f < 2; ++f) {
                uint32_t off = sw128((uint32_t)((wm * 32 + f * 16 + arow) * 128 + achk * 16));
                LDSM4(ah[f], sbuf + off);
                LDSM4(al[f], sbuf + 8192 + off);
            }
            const int brow = (lane >> 4) * 8 + (lane & 7);
            const int bchk = klo + ((lane >> 3) & 1);
#pragma unroll
            for (int p = 0; p < 2; ++p) {
                uint32_t off = sw128((uint32_t)((wn * 32 + p * 16 + brow) * 128 + bchk * 16));
                uint32_t r[4];
                LDSM4(r, sbuf + 16384 + off);
                bh[2*p][0] = r[0]; bh[2*p][1] = r[1];
                bh[2*p+1][0] = r[2]; bh[2*p+1][1] = r[3];
                LDSM4(r, sbuf + 32768 + off);
                bl[2*p][0] = r[0]; bl[2*p][1] = r[1];
                bl[2*p+1][0] = r[2]; bl[2*p+1][1] = r[3];
            }
#pragma unroll
            for (int f = 0; f < 2; ++f)
#pragma unroll
                for (int n = 0; n < 4; ++n) {
                    MMA16816(acc[f][n], ah[f], bh[n]);
                    MMA16816(acc[f][n], ah[f], bl[n]);
                    MMA16816(acc[f][n], al[f], bh[n]);
                }
        }
        __syncthreads();
    }
}

// Fused q/k/v projection. grid (64, 10).
__global__ void __launch_bounds__(256, 2) gemm_qkv()
{
    extern __shared__ char smem[];
    const int y = blockIdx.y;
    int widx, brow;
    if (y < 3)      { widx = 0; brow = 128 + y * 128; }
    else if (y < 6) { widx = 1; brow = 128 + (y - 3) * 128; }
    else            { widx = 2; brow = (y - 6) * 128; }
    const int m0 = blockIdx.x * 64;

    float acc[2][4][4] = {};
    mainloop64(g_xh, g_xl,
               g_wh + (size_t)widx * NN + (size_t)brow * 512,
               g_wl + (size_t)widx * NN + (size_t)brow * 512,
               m0, smem, acc);

    const int tid = threadIdx.x, lane = tid & 31;
    const int wid = tid >> 5;
    const int wm = wid & 1, wn = wid >> 1;
    const int r0 = m0 + wm * 32 + (lane >> 2);
    const int c0 = wn * 32 + (lane & 3) * 2;

    if (y < 6) {
        __nv_bfloat16* dh = widx ? g_kh : g_qh;
        __nv_bfloat16* dl = widx ? g_kl : g_ql;
        const int cp0 = (brow - 128) + c0;
#pragma unroll
        for (int f = 0; f < 2; ++f)
#pragma unroll
            for (int n = 0; n < 4; ++n) {
#pragma unroll
                for (int hr = 0; hr < 2; ++hr) {
                    const int row = r0 + f * 16 + hr * 8;
                    float v0 = acc[f][n][hr*2], v1 = acc[f][n][hr*2+1];
                    __nv_bfloat16 h0 = __float2bfloat16(v0), h1 = __float2bfloat16(v1);
                    size_t o = (size_t)row * QKW + cp0 + n * 8;
                    *(__nv_bfloat162*)(dh + o) = __halves2bfloat162(h0, h1);
                    *(__nv_bfloat162*)(dl + o) = __halves2bfloat162(
                        __float2bfloat16(v0 - __bfloat162float(h0)),
                        __float2bfloat16(v1 - __bfloat162float(h1)));
                }
            }
    } else {
#pragma unroll
        for (int f = 0; f < 2; ++f)
#pragma unroll
            for (int n = 0; n < 4; ++n) {
                float* p0 = g_v + (size_t)(r0 + f * 16) * 512 + brow + c0 + n * 8;
                *(float2*)p0 = make_float2(acc[f][n][0], acc[f][n][1]);
                *(float2*)(p0 + 8 * 512) = make_float2(acc[f][n][2], acc[f][n][3]);
            }
    }
}

// Output projection: out = a @ wo^T. grid (64, 4).
__global__ void __launch_bounds__(256, 2) gemm_out(float* __restrict__ out)
{
    extern __shared__ char smem[];
    const int brow = blockIdx.y * 128;
    const int m0 = blockIdx.x * 64;
    float acc[2][4][4] = {};
    mainloop64(g_ah, g_al,
               g_wh + 3ull * NN + (size_t)brow * 512,
               g_wl + 3ull * NN + (size_t)brow * 512,
               m0, smem, acc);
    const int tid = threadIdx.x, lane = tid & 31;
    const int wid = tid >> 5;
    const int wm = wid & 1, wn = wid >> 1;
    const int r0 = m0 + wm * 32 + (lane >> 2);
    const int c0 = brow + wn * 32 + (lane & 3) * 2;
#pragma unroll
    for (int f = 0; f < 2; ++f)
#pragma unroll
        for (int n = 0; n < 4; ++n) {
            float* p0 = out + (size_t)(r0 + f * 16) * 512 + c0 + n * 8;
            *(float2*)p0 = make_float2(acc[f][n][0], acc[f][n][1]);
            *(float2*)(p0 + 8 * 512) = make_float2(acc[f][n][2], acc[f][n][3]);
        }
}

// ================= gemm_w via MMA: w1 = q.sk^T, w2t = k.sq^T ======================
#define GW_SMEM (2*49152)
__global__ void __launch_bounds__(256, 2) gemm_w_mma()
{
    extern __shared__ char smem[];
    const uint32_t sb = smem_u32(smem);
    const int tid = threadIdx.x, lane = tid & 31;
    const int wm = (tid >> 5) & 3, wn = tid >> 7;
    const int second = blockIdx.z;
    const int bh_ = blockIdx.y;
    const int b = bh_ / 3, hm = bh_ % 3;
    const int m0 = blockIdx.x * 128;

    const __nv_bfloat16* Ah = (second ? g_kh : g_qh) + (size_t)b*Tv*QKW + hm*HDv;
    const __nv_bfloat16* Al = (second ? g_kl : g_ql) + (size_t)b*Tv*QKW + hm*HDv;
    const __nv_bfloat16* Bh = (second ? g_sqh : g_skh) + (size_t)bh_*Lv*HDv;
    const __nv_bfloat16* Bl = (second ? g_sql : g_skl) + (size_t)bh_*Lv*HDv;
    float* C = (second ? g_w2t : g_w1) + ((size_t)((b*4+hm+1)*Tv) + m0) * Lv;

    float acc[2][4][4] = {};

    auto load_stage = [&](int kc, uint32_t dstb) {
#pragma unroll
        for (int t = 0; t < 2; ++t) {
            const __nv_bfloat16* base = t ? Al : Ah;
#pragma unroll
            for (int j = 0; j < 4; ++j) {
                int idx = j * 256 + tid;
                int row = idx >> 3, c = idx & 7;
                CP16(dstb + t * 16384 + sw128((uint32_t)(row * 128 + c * 16)),
                     base + (size_t)(m0 + row) * QKW + kc * 64 + c * 8);
            }
        }
#pragma unroll
        for (int t = 0; t < 2; ++t) {
            const __nv_bfloat16* base = t ? Bl : Bh;
#pragma unroll
            for (int j = 0; j < 2; ++j) {
                int idx = j * 256 + tid;
                int row = idx >> 3, c = idx & 7;
                CP16(dstb + 32768 + t * 8192 + sw128((uint32_t)(row * 128 + c * 16)),
                     base + (size_t)row * HDv + kc * 64 + c * 8);
            }
        }
    };

    load_stage(0, sb); CP_COMMIT();
    load_stage(1, sb + 49152); CP_COMMIT();

    for (int kc = 0; kc < 2; ++kc) {
        if (kc == 0) asm volatile("cp.async.wait_group 1;" ::: "memory");
        else         asm volatile("cp.async.wait_group 0;" ::: "memory");
        __syncthreads();
        const uint32_t sbuf = sb + kc * 49152;
#pragma unroll
        for (int kk = 0; kk < 4; ++kk) {
            const int klo = kk * 2;
            uint32_t ah[2][4], al[2][4], bh[4][2], bl[4][2];
            const int arow = ((lane >> 3) & 1) * 8 + (lane & 7);
            const int achk = klo + (lane >> 4);
#pragma unroll
            for (int f = 0; f < 2; ++f) {
                uint32_t off = sw128((uint32_t)((wm * 32 + f * 16 + arow) * 128 + achk * 16));
                LDSM4(ah[f], sbuf + off);
                LDSM4(al[f], sbuf + 16384 + off);
            }
            const int brow = (lane >> 4) * 8 + (lane & 7);
            const int bchk = klo + ((lane >> 3) & 1);
#pragma unroll
            for (int p = 0; p < 2; ++p) {
                uint32_t off = sw128((uint32_t)((wn * 32 + p * 16 + brow) * 128 + bchk * 16));
                uint32_t r[4];
                LDSM4(r, sbuf + 32768 + off);
                bh[2*p][0] = r[0]; bh[2*p][1] = r[1];
                bh[2*p+1][0] = r[2]; bh[2*p+1][1] = r[3];
                LDSM4(r, sbuf + 40960 + off);
                bl[2*p][0] = r[0]; bl[2*p][1] = r[1];
                bl[2*p+1][0] = r[2]; bl[2*p+1][1] = r[3];
            }
#pragma unroll
            for (int f = 0; f < 2; ++f)
#pragma unroll
                for (int n = 0; n < 4; ++n) {
                    MMA16816(acc[f][n], ah[f], bh[n]);
                    MMA16816(acc[f][n], ah[f], bl[n]);
                    MMA16816(acc[f][n], al[f], bh[n]);
                }
        }
        __syncthreads();
    }

    const int r0 = wm * 32 + (lane >> 2);
    const int c0 = wn * 32 + (lane & 3) * 2;
#pragma unroll
    for (int f = 0; f < 2; ++f)
#pragma unroll
        for (int n = 0; n < 4; ++n) {
            float* p0 = C + (size_t)(r0 + f * 16) * Lv + c0 + n * 8;
            *(float2*)p0 = make_float2(acc[f][n][0], acc[f][n][1]);
            *(float2*)(p0 + 8 * Lv) = make_float2(acc[f][n][2], acc[f][n][3]);
        }
}

// ================= fused fp32 -> (hi,lo) bf16 split (x + 4 weights) =================
__global__ void split_all(const float2* __restrict__ x,
                          const float2* __restrict__ w0, const float2* __restrict__ w1,
                          const float2* __restrict__ w2, const float2* __restrict__ w3)
{
    int bid = blockIdx.x;
    const float2* src;
    __nv_bfloat162 *dh, *dl;
    size_t i;
    if (bid < 4096) {
        i = (size_t)bid * 256 + threadIdx.x;
        src = x; dh = (__nv_bfloat162*)g_xh; dl = (__nv_bfloat162*)g_xl;
    } else {
        int r = bid - 4096;
        int widx = r >> 9;
        i = (size_t)(r & 511) * 256 + threadIdx.x;
        src = (widx == 0) ? w0 : (widx == 1) ? w1 : (widx == 2) ? w2 : w3;
        dh = (__nv_bfloat162*)g_wh + (size_t)widx * (NN/2);
        dl = (__nv_bfloat162*)g_wl + (size_t)widx * (NN/2);
    }
    float2 v = src[i];
    __nv_bfloat16 h0 = __float2bfloat16(v.x);
    __nv_bfloat16 h1 = __float2bfloat16(v.y);
    dh[i] = __halves2bfloat162(h0, h1);
    dl[i] = __halves2bfloat162(__float2bfloat16(v.x - __bfloat162float(h0)),
                               __float2bfloat16(v.y - __bfloat162float(h1)));
}

// ================= lam scalar =================
__global__ void lam_kernel(const float* __restrict__ lq1, const float* __restrict__ lk1,
                           const float* __restrict__ lq2, const float* __restrict__ lk2,
                           const int* __restrict__ lptr)
{
    __shared__ float r1[128], r2[128];
    int t = threadIdx.x;
    r1[t] = lq1[t]*lk1[t];
    r2[t] = lq2[t]*lk2[t];
    __syncthreads();
    for (int o = 64; o; o >>= 1) {
        if (t < o) { r1[t] += r1[t+o]; r2[t] += r2[t+o]; }
        __syncthreads();
    }
    if (t == 0) {
        float lam_init = 0.8f - 0.6f*expf(-0.3f*(float)lptr[0]);
        g_scal[0] = expf(r1[0]) - expf(r2[0]) + lam_init;
        g_scal[1] = 1.0f - lam_init;
    }
}

// ================= sq / sk: warp-per-task reconstruct+normalize+scale+split ========
// 768 tasks = which(2) x b(2) x hm(3) x j(64). grid 96 x 256 (8 warps/block).
__global__ void __launch_bounds__(256) sqsk_kernel(const int* __restrict__ landmark,
                                                   const float* __restrict__ m1,
                                                   const float* __restrict__ m2)
{
    int task = blockIdx.x * 8 + (threadIdx.x >> 5);
    int lane = threadIdx.x & 31;
    int which = task & 1;
    int rest = task >> 1;
    int j  = rest & 63;
    int hm = (rest >> 6) % 3;
    int b  = rest / 192;
    int tok = landmark[j];

    size_t off = (size_t)(b*Tv + tok)*QKW + hm*HDv + lane*4;
    const __nv_bfloat16* ph = which ? g_kh : g_qh;
    const __nv_bfloat16* pl = which ? g_kl : g_ql;
    float v[4];
#pragma unroll
    for (int e = 0; e < 4; ++e)
        v[e] = __bfloat162float(ph[off+e]) + __bfloat162float(pl[off+e]);

    float ss = v[0]*v[0] + v[1]*v[1] + v[2]*v[2] + v[3]*v[3];
#pragma unroll
    for (int o = 16; o; o >>= 1) ss += __shfl_xor_sync(0xffffffffu, ss, o);

    float scale = (which ? m2[(hm+1)*Lv + j] : m1[(hm+1)*Lv + j]) * rsqrtf(ss);
    __nv_bfloat16* dh = which ? g_skh : g_sqh;
    __nv_bfloat16* dl = which ? g_skl : g_sql;
    size_t d = ((size_t)(b*3 + hm)*Lv + j)*HDv + lane*4;
#pragma unroll
    for (int e = 0; e < 4; ++e) {
        float o = v[e] * scale;
        __nv_bfloat16 h = __float2bfloat16(o);
        dh[d+e] = h;
        dl[d+e] = __float2bfloat16(o - __bfloat162float(h));
    }
}

// ================= symmetric mask -> per-row CSR =================
__global__ void mask_kernel(const int* __restrict__ rns)
{
    int warp = (blockIdx.x * blockDim.x + threadIdx.x) >> 5;
    int lane = threadIdx.x & 31;
    int b = warp >> 11, i = warp & (Tv-1);
    const int* row = rns + (size_t)warp * KIv;
    int j = row[lane];
    bool dup = false;
#pragma unroll
    for (int k2 = 0; k2 < 32; ++k2) {
        int jj = __shfl_sync(0xffffffffu, j, k2);
        if (k2 < lane && jj == j) dup = true;
    }
    bool mem = false;
    const int* rj = rns + (size_t)(b*Tv + j)*KIv;
#pragma unroll
    for (int m = 0; m < 32; ++m) if (rj[m] == i) mem = true;
    bool valid = (!dup) && mem;
    unsigned bal = __ballot_sync(0xffffffffu, valid);
    if (valid) {
        int pos = __popc(bal & ((1u << lane) - 1u));
        g_cols[(size_t)warp*KIv + pos] = j;
    }
    if (lane == 0) g_cnt[warp] = __popc(bal);
}

// ================= column partial sums of v (zero-nnz rows) =================
__global__ void colsumA()
{
    int g = blockIdx.x*256 + threadIdx.x;
    int chunk = g >> 10;
    int c = g & 1023;
    int b = c >> 9, col = c & 511;
    const float* p = g_v + (size_t)(b*Tv + chunk*256)*NXv + col;
    float s = 0.f;
    for (int t = 0; t < 256; ++t) s += p[(size_t)t*NXv];
    g_vpart[g] = s;
}

// ================= sparse attention rows + wmix + RMSNorm + bf16 split ===========
__global__ void __launch_bounds__(256) attn_rows(const float* __restrict__ rms_g)
{
    const int r = blockIdx.x;
    const int b = r >> 11;
    const int i = r & (Tv-1);
    const int tid = threadIdx.x;
    __shared__ int   scols[KIv];
    __shared__ float sw[3][KIv];
    __shared__ float c0[KIv], c1[KIv];
    __shared__ float red[512];
    const int cnt = g_cnt[r];
    if (tid < KIv && tid < cnt) scols[tid] = g_cols[(size_t)r*KIv + tid];
    __syncthreads();
    const float lam = g_scal[0];
    const int wid = tid >> 5, lane = tid & 31;

    for (int task = wid; task < 3*cnt; task += 8) {
        int hm = task % 3, j = task / 3, h = hm + 1;
        const float* w1p = g_w1  + ((size_t)((b*4+h)*Tv + i)        << 6);
        const float* w2p = g_w2t + ((size_t)((b*4+h)*Tv + scols[j]) << 6);
        float s = w1p[lane]*w2p[lane] + w1p[lane+32]*w2p[lane+32];
#pragma unroll
        for (int o = 16; o; o >>= 1) s += __shfl_xor_sync(0xffffffffu, s, o);
        if (lane == 0) sw[hm][j] = s;
    }
    __syncthreads();

    if (wid == 0 && cnt > 0) {
        float p[3];
#pragma unroll
        for (int hm = 0; hm < 3; ++hm) {
            float x = (lane < cnt) ? sw[hm][lane] : -INFINITY;
            float mx = x;
#pragma unroll
            for (int o = 16; o; o >>= 1) mx = fmaxf(mx, __shfl_xor_sync(0xffffffffu, mx, o));
            float e = (lane < cnt) ? expf(x - mx) : 0.f;
            float sm = e;
#pragma unroll
            for (int o = 16; o; o >>= 1) sm += __shfl_xor_sync(0xffffffffu, sm, o);
            p[hm] = e / sm;
        }
        if (lane < cnt) {
            c0[lane] = (1.f - lam)*p[1] - lam*p[0];
            c1[lane] = p[1] - p[0] + (1.f - 2.f*lam)*p[2];
        }
    }
    __syncthreads();

    float s0 = 0.f, s1 = 0.f;
    if (cnt > 0) {
#pragma unroll 4
        for (int j = 0; j < cnt; ++j) {
            const float* vp = g_v + ((size_t)(b*Tv + scols[j]) << 9);
            s0 += c0[j] * vp[tid];
            s1 += c1[j] * vp[tid + 256];
        }
    } else {
        float u = (1.f - 2.f*lam) * (1.f/(float)Tv);
        float t0 = 0.f, t1 = 0.f;
#pragma unroll
        for (int ch = 0; ch < 8; ++ch) {
            t0 += g_vpart[ch*1024 + b*512 + tid];
            t1 += g_vpart[ch*1024 + b*512 + tid + 256];
        }
        s0 = u * t0;
        s1 = u * t1;
    }

    red[tid]       = s0*s0;
    red[tid + 256] = s1*s1;
    __syncthreads();
#pragma unroll
    for (int o = 128; o; o >>= 1) {
        if (tid < o) { red[tid] += red[tid+o]; red[256+tid] += red[256+tid+o]; }
        __syncthreads();
    }
    float onem = g_scal[1];
    float g = rms_g[tid];
    float a0 = s0 * rsqrtf(red[0]  *(1.f/256.f) + 1e-5f) * g * onem;
    float a1 = s1 * rsqrtf(red[256]*(1.f/256.f) + 1e-5f) * g * onem;
    __nv_bfloat16 h0 = __float2bfloat16(a0);
    __nv_bfloat16 h1 = __float2bfloat16(a1);
    size_t o0 = (size_t)r*NXv + tid, o1 = o0 + 256;
    g_ah[o0] = h0;                                   g_ah[o1] = h1;
    g_al[o0] = __float2bfloat16(a0 - __bfloat162float(h0));
    g_al[o1] = __float2bfloat16(a1 - __bfloat162float(h1));
}

// ================= launch (multi-stream fork/join, graph-capture safe) =============
extern "C" void kernel_launch(void* const* d_in, const int* in_sizes, int n_in,
                              void* d_out, int out_size)
{
    const float* x    = (const float*)d_in[0];
    const float* wq   = (const float*)d_in[1];
    const float* wk   = (const float*)d_in[2];
    const float* wv   = (const float*)d_in[3];
    const float* wo   = (const float*)d_in[4];
    const float* m1   = (const float*)d_in[5];
    const float* m2   = (const float*)d_in[6];
    const float* lq1  = (const float*)d_in[7];
    const float* lk1  = (const float*)d_in[8];
    const float* lq2  = (const float*)d_in[9];
    const float* lk2  = (const float*)d_in[10];
    const float* rmsg = (const float*)d_in[11];
    const int*   lp   = (const int*)d_in[12];
    const int*   rns  = (const int*)d_in[14];
    const int*   lmk  = (const int*)d_in[15];
    float* out = (float*)d_out;

    static cudaStream_t s1 = nullptr, s2 = nullptr;
    static cudaEvent_t e_fork = nullptr, e_mask = nullptr, e_qkv = nullptr, e_cols = nullptr;
    static int inited = 0;
    if (!inited) {
        cudaStreamCreateWithFlags(&s1, cudaStreamNonBlocking);
        cudaStreamCreateWithFlags(&s2, cudaStreamNonBlocking);
        cudaEventCreateWithFlags(&e_fork, cudaEventDisableTiming);
        cudaEventCreateWithFlags(&e_mask, cudaEventDisableTiming);
        cudaEventCreateWithFlags(&e_qkv,  cudaEventDisableTiming);
        cudaEventCreateWithFlags(&e_cols, cudaEventDisableTiming);
        cudaFuncSetAttribute(gemm_qkv,   cudaFuncAttributeMaxDynamicSharedMemorySize, GEMM_SMEM_TOTAL);
        cudaFuncSetAttribute(gemm_out,   cudaFuncAttributeMaxDynamicSharedMemorySize, GEMM_SMEM_TOTAL);
        cudaFuncSetAttribute(gemm_w_mma, cudaFuncAttributeMaxDynamicSharedMemorySize, GW_SMEM);
        inited = 1;
    }

    // fork: mask depends only on the input rns -> run on s1 concurrently
    cudaEventRecord(e_fork, 0);
    cudaStreamWaitEvent(s1, e_fork, 0);
    mask_kernel<<<Bv*Tv*32/256, 256, 0, s1>>>(rns);
    cudaEventRecord(e_mask, s1);

    // main chain
    lam_kernel<<<1, 128>>>(lq1, lk1, lq2, lk2, lp);
    split_all<<<6144, 256>>>((const float2*)x, (const float2*)wq, (const float2*)wk,
                             (const float2*)wv, (const float2*)wo);
    gemm_qkv<<<dim3(Bv*Tv/64, 10), 256, GEMM_SMEM_TOTAL>>>();
    cudaEventRecord(e_qkv, 0);

    // fork: colsumA on s2 concurrent with sqsk -> gemm_w on main
    cudaStreamWaitEvent(s2, e_qkv, 0);
    colsumA<<<32, 256, 0, s2>>>();
    cudaEventRecord(e_cols, s2);

    sqsk_kernel<<<96, 256>>>(lmk, m1, m2);
    gemm_w_mma<<<dim3(Tv/128, Bv*3, 2), 256, GW_SMEM>>>();

    // join
    cudaStreamWaitEvent(0, e_mask, 0);
    cudaStreamWaitEvent(0, e_cols, 0);
    attn_rows<<<Bv*Tv, 256>>>(rmsg);
    gemm_out<<<dim3(Bv*Tv/64, 4), 256, GEMM_SMEM_TOTAL>>>(out);
}